// round 8
// baseline (speedup 1.0000x reference)
#include <cuda_runtime.h>
#include <cstdint>
#include <cstddef>
#include <math.h>

using ull = unsigned long long;
#define DEV_INLINE __device__ __forceinline__

DEV_INLINE void ffma2(ull &acc, ull a, ull w) {
    asm("fma.rn.f32x2 %0, %1, %2, %0;" : "+l"(acc) : "l"(a), "l"(w));
}
DEV_INLINE ull pack2(float lo, float hi) {
    ull r; asm("mov.b64 %0, {%1, %2};" : "=l"(r) : "f"(lo), "f"(hi)); return r;
}
DEV_INLINE void unpack2(ull v, float &lo, float &hi) {
    asm("mov.b64 {%0, %1}, %2;" : "=f"(lo), "=f"(hi) : "l"(v));
}
DEV_INLINE ull dup_lo(ull v) { float a, b; unpack2(v, a, b); return pack2(a, a); }
DEV_INLINE ull dup_hi(ull v) { float a, b; unpack2(v, a, b); return pack2(b, b); }

constexpr int FH = 512, FW = 1280;

// ---------------------------------------------------------------------------
// Scratch arena. Zero-initialized at module load; conv halos are NEVER written
// by any kernel, so they remain zero across all calls (deterministic).
// ---------------------------------------------------------------------------
__device__ float g_scratch[41000000];

// ---------------------------------------------------------------------------
// 3x3x3 SAME conv3d on ZERO-PADDED input [B,CIN,D+2,H+2,W+2], writes padded
// interior of out. cout-pairs in f32x2 lanes, LDG.64 input loads, LDS.128
// weights. SINGLE-buffered (regs <= 64 via launch_bounds -> 8 blocks/SM;
// LDG latency is covered cross-warp by high occupancy).
// ---------------------------------------------------------------------------
template<int CIN, int COUT, int COP, int D, int H, int W, bool RELU>
__global__ void __launch_bounds__(128, 8) conv3d_p(
    const float* __restrict__ in, const float* __restrict__ wgt,
    float* __restrict__ out)
{
    constexpr int PW = W + 2, PH = H + 2, PD = D + 2;
    constexpr int PLANE = PH * PW;
    constexpr int CHS = PD * PLANE;
    constexpr int HP = H / 2, WP = W / 2;
    constexpr int SPB = 8 * D * HP * WP / 128;
    constexpr int NW = CIN * 27 * COP;

    __shared__ alignas(16) float2 ws[NW];
    const int g = blockIdx.x / SPB;
    const int co_base = g * 2 * COP;
    for (int i = threadIdx.x; i < NW; i += 128) {
        int cp  = i % COP;
        int pos = (i / COP) % 27;
        int ci  = i / (COP * 27);
        float2 wv;
        wv.x = wgt[((co_base + 2 * cp)     * CIN + ci) * 27 + pos];
        wv.y = wgt[((co_base + 2 * cp + 1) * CIN + ci) * 27 + pos];
        ws[(ci * 27 + pos) * COP + cp] = wv;
    }
    __syncthreads();

    int sidx = (blockIdx.x % SPB) * 128 + threadIdx.x;
    int wp = sidx % WP;
    int t  = sidx / WP;
    int hp = t % HP;
    t /= HP;
    int d = t % D;
    int b = t / D;
    int h0 = hp * 2, w0 = wp * 2;

    ull acc[4][COP];
    #pragma unroll
    for (int p = 0; p < 4; p++)
        #pragma unroll
        for (int c = 0; c < COP; c++) acc[p][c] = 0ULL;

    const float* base = in + (size_t)b * CIN * CHS
                           + (size_t)d * PLANE + (size_t)h0 * PW + w0;
    const ull* wsp = reinterpret_cast<const ull*>(ws);

    // patch rows are 8B-aligned (w0 even, PW even, all strides even)
    auto loadr = [&](ull dst[8], const float* q) {
        #pragma unroll
        for (int r = 0; r < 4; r++) {
            dst[2 * r]     = *reinterpret_cast<const ull*>(q + r * PW);
            dst[2 * r + 1] = *reinterpret_cast<const ull*>(q + r * PW + 2);
        }
    };
    auto addr = [&](int it) {
        return base + (size_t)(it / 3) * CHS + (size_t)(it % 3) * PLANE;
    };
    auto compute = [&](const ull buf[8], const ull* wt) {
        ull vp[4][4];
        #pragma unroll
        for (int r = 0; r < 4; r++) {
            vp[r][0] = dup_lo(buf[2 * r]);
            vp[r][1] = dup_hi(buf[2 * r]);
            vp[r][2] = dup_lo(buf[2 * r + 1]);
            vp[r][3] = dup_hi(buf[2 * r + 1]);
        }
        #pragma unroll
        for (int kh = 0; kh < 3; kh++) {
            #pragma unroll
            for (int kw = 0; kw < 3; kw++) {
                const ull* wkk = wt + (kh * 3 + kw) * COP;
                #pragma unroll
                for (int cp = 0; cp < COP; cp += 2) {
                    ulonglong2 wv = *reinterpret_cast<const ulonglong2*>(wkk + cp);
                    ffma2(acc[0][cp], vp[kh][kw],         wv.x);
                    ffma2(acc[1][cp], vp[kh][kw + 1],     wv.x);
                    ffma2(acc[2][cp], vp[kh + 1][kw],     wv.x);
                    ffma2(acc[3][cp], vp[kh + 1][kw + 1], wv.x);
                    ffma2(acc[0][cp + 1], vp[kh][kw],         wv.y);
                    ffma2(acc[1][cp + 1], vp[kh][kw + 1],     wv.y);
                    ffma2(acc[2][cp + 1], vp[kh + 1][kw],     wv.y);
                    ffma2(acc[3][cp + 1], vp[kh + 1][kw + 1], wv.y);
                }
            }
        }
    };

    constexpr int NIT = 3 * CIN;
    ull buf[8];
    #pragma unroll 1
    for (int it = 0; it < NIT; ++it) {
        loadr(buf, addr(it));
        compute(buf, wsp + it * 9 * COP);
    }

    size_t obase = ((size_t)(b * COUT) * PD + (d + 1)) * PLANE
                 + (size_t)(h0 + 1) * PW + (w0 + 1);
    #pragma unroll
    for (int cp = 0; cp < COP; cp++) {
        size_t o0 = obase + (size_t)(co_base + 2 * cp) * CHS;
        #pragma unroll
        for (int pp = 0; pp < 4; pp++) {
            float x, y;
            unpack2(acc[pp][cp], x, y);
            if (RELU) { x = fmaxf(x, 0.f); y = fmaxf(y, 0.f); }
            size_t o = o0 + (size_t)(pp >> 1) * PW + (pp & 1);
            out[o] = x;
            out[o + CHS] = y;
        }
    }
}

// ---------------------------------------------------------------------------
// Final conv: CIN -> 1 channel, padded input, UNPADDED output, no ReLU.
// 1x2 outputs per thread (small patch, small regs, double grid vs 2x2).
// ---------------------------------------------------------------------------
template<int CIN, int D, int H, int W>
__global__ void __launch_bounds__(128) conv3d_s(
    const float* __restrict__ in, const float* __restrict__ wgt,
    float* __restrict__ out)
{
    constexpr int PW = W + 2, PH = H + 2, PD = D + 2;
    constexpr int PLANE = PH * PW;
    constexpr int CHS = PD * PLANE;
    constexpr int WP = W / 2;

    __shared__ float ws[CIN * 27];
    for (int i = threadIdx.x; i < CIN * 27; i += 128)
        ws[i] = wgt[i];
    __syncthreads();

    int sidx = blockIdx.x * 128 + threadIdx.x;   // 8*D*H*WP threads
    int wp = sidx % WP;
    int t  = sidx / WP;
    int h  = t % H;
    t /= H;
    int d = t % D;
    int b = t / D;
    int w0 = wp * 2;

    float sacc[2] = {0.f, 0.f};
    const float* base = in + (size_t)b * CIN * CHS
                           + (size_t)d * PLANE + (size_t)h * PW + w0;

    #pragma unroll 1
    for (int it = 0; it < 3 * CIN; ++it) {
        const float* q = base + (size_t)(it / 3) * CHS + (size_t)(it % 3) * PLANE;
        float v[3][4];
        #pragma unroll
        for (int r = 0; r < 3; r++) {
            ull a = *reinterpret_cast<const ull*>(q + r * PW);
            ull c = *reinterpret_cast<const ull*>(q + r * PW + 2);
            unpack2(a, v[r][0], v[r][1]);
            unpack2(c, v[r][2], v[r][3]);
        }
        const float* wt = ws + (it / 3) * 27 + (it % 3) * 9;
        #pragma unroll
        for (int kh = 0; kh < 3; kh++) {
            #pragma unroll
            for (int kw = 0; kw < 3; kw++) {
                float wv = wt[kh * 3 + kw];
                sacc[0] = fmaf(v[kh][kw],     wv, sacc[0]);
                sacc[1] = fmaf(v[kh][kw + 1], wv, sacc[1]);
            }
        }
    }

    size_t bo = ((size_t)b * D + d) * (H * W) + (size_t)h * W + w0;
    out[bo]     = sacc[0];
    out[bo + 1] = sacc[1];
}

// ---------------------------------------------------------------------------
// Scale-0 L1 cost volume -> PADDED cost buffer [B,1,14,34,82]
// ---------------------------------------------------------------------------
__global__ void cost0_k(const float* __restrict__ fl, const float* __restrict__ fr,
                        float* __restrict__ cost)
{
    int idx = blockIdx.x * 256 + threadIdx.x;   // 8*12*32*80
    int w  = idx % 80;
    int h  = (idx / 80) % 32;
    int dd = (idx / (80 * 32)) % 12;
    int b  = idx / (80 * 32 * 12);
    int src = w - dd;
    const float* flb = fl + (size_t)b * 8 * 32 * 80 + h * 80;
    const float* frb = fr + (size_t)b * 8 * 32 * 80 + h * 80;
    float s = 0.f;
    #pragma unroll
    for (int c = 0; c < 8; c++) {
        float a = flb[c * 32 * 80 + w];
        float r = (src >= 0) ? frb[c * 32 * 80 + src] : 0.f;
        s += fabsf(a - r);
    }
    cost[((size_t)b * 14 + dd + 1) * (34 * 82) + (h + 1) * 82 + (w + 1)] = s;
}

// ---------------------------------------------------------------------------
// Residual cost volume -> PADDED cost buffer [B,1,7,H+2,W+2]
// ---------------------------------------------------------------------------
template<int H, int W>
__global__ void costres_k(const float* __restrict__ fl, const float* __restrict__ fr,
                          const float* __restrict__ wflow, float* __restrict__ cost)
{
    constexpr int PW = W + 2, PH = H + 2;
    int idx = blockIdx.x * 256 + threadIdx.x;   // 8*5*H*W
    int w = idx % W;
    int h = (idx / W) % H;
    int s = (idx / (W * H)) % 5;
    int b = idx / (W * H * 5);
    float disp = wflow[((size_t)b * H + h) * W + w];
    float sd = disp - (float)(s - 2);
    float xs = (float)w - sd;
    float x0f = floorf(xs);
    float w1 = xs - x0f;
    int x0 = (int)x0f;
    bool in0 = (x0 >= 0) && (x0 <= W - 1);
    bool in1 = (x0 + 1 >= 0) && (x0 + 1 <= W - 1);
    int i0 = min(max(x0, 0), W - 1);
    int i1 = min(max(x0 + 1, 0), W - 1);
    const float* flb = fl + ((size_t)b * 8 * H + h) * W;
    const float* frb = fr + ((size_t)b * 8 * H + h) * W;
    float acc = 0.f;
    #pragma unroll
    for (int c = 0; c < 8; c++) {
        float a  = flb[c * H * W + w];
        float v0 = in0 ? frb[c * H * W + i0] : 0.f;
        float v1 = in1 ? frb[c * H * W + i1] : 0.f;
        acc += fabsf(a - (v0 * (1.f - w1) + v1 * w1));
    }
    cost[((size_t)b * 7 + s + 1) * (PH * PW) + (h + 1) * PW + (w + 1)] = acc;
}

// ---------------------------------------------------------------------------
// Softargmin disparity regression (reads UNPADDED cost)
// ---------------------------------------------------------------------------
template<int DT, int START, int H, int W>
__global__ void dispreg_k(const float* __restrict__ cost, float* __restrict__ dout,
                          float scale)
{
    int idx = blockIdx.x * 256 + threadIdx.x;   // 8*H*W
    int w = idx % W;
    int h = (idx / W) % H;
    int b = idx / (W * H);
    float c[DT];
    #pragma unroll
    for (int i = 0; i < DT; i++)
        c[i] = cost[(((size_t)b * DT + i) * H + h) * W + w];
    float mn = c[0];
    #pragma unroll
    for (int i = 1; i < DT; i++) mn = fminf(mn, c[i]);
    float s = 0.f, num = 0.f;
    #pragma unroll
    for (int i = 0; i < DT; i++) {
        float p = expf(mn - c[i]);
        s += p;
        num += p * (float)(START + i);
    }
    dout[idx] = num / s * scale;
}

// ---------------------------------------------------------------------------
// Bilinear upsample to 512x1280 (jax half-pixel), 4 px/thread (float4 I/O),
// optional add of previous full-res pred, optional depth output.
// ---------------------------------------------------------------------------
template<int IH, int IW, bool ADD, bool DEPTH>
__global__ void up_k(const float* __restrict__ src, const float* __restrict__ addsrc,
                     float* __restrict__ outp, float* __restrict__ depthp)
{
    int idx = blockIdx.x * 256 + threadIdx.x;   // 8*512*320
    int oq = idx % (FW / 4);
    int oy = (idx / (FW / 4)) % FH;
    int b  = idx / ((FW / 4) * FH);

    float fy = ((float)oy + 0.5f) * ((float)IH / (float)FH) - 0.5f;
    fy = fminf(fmaxf(fy, 0.f), (float)(IH - 1));
    int y0 = (int)fy; float gy = fy - (float)y0; int y1 = min(y0 + 1, IH - 1);
    const float* sb = src + (size_t)b * IH * IW;
    const float* r0 = sb + y0 * IW;
    const float* r1 = sb + y1 * IW;

    size_t base = ((size_t)b * FH + oy) * FW + oq * 4;
    float4 res, dep;
    float* rp = reinterpret_cast<float*>(&res);
    float* dp = reinterpret_cast<float*>(&dep);
    #pragma unroll
    for (int j = 0; j < 4; j++) {
        int ox = oq * 4 + j;
        float fx = ((float)ox + 0.5f) * ((float)IW / (float)FW) - 0.5f;
        fx = fminf(fmaxf(fx, 0.f), (float)(IW - 1));
        int x0 = (int)fx; float gx = fx - (float)x0; int x1 = min(x0 + 1, IW - 1);
        float v = (r0[x0] * (1.f - gx) + r0[x1] * gx) * (1.f - gy)
                + (r1[x0] * (1.f - gx) + r1[x1] * gx) * gy;
        rp[j] = v;
    }
    if (ADD) {
        float4 a = *reinterpret_cast<const float4*>(addsrc + base);
        res.x += a.x; res.y += a.y; res.z += a.z; res.w += a.w;
    }
    *reinterpret_cast<float4*>(outp + base) = res;
    if (DEPTH) {
        #pragma unroll
        for (int j = 0; j < 4; j++)
            dp[j] = fminf(fmaxf(64.0f / fabsf(rp[j]), 0.1f), 100.0f);
        *reinterpret_cast<float4*>(depthp + base) = dep;
    }
}

// ---------------------------------------------------------------------------
// Separable antialiased downsample (jax triangle kernel, width R, per-axis
// normalized). Pass 1: horizontal 1280 -> OW at full height 512.
// ---------------------------------------------------------------------------
template<int R, int OW>
__global__ void down_h(const float* __restrict__ src, float* __restrict__ tmp)
{
    int idx = blockIdx.x * 256 + threadIdx.x;   // 8*512*OW
    int ox = idx % OW;
    int y  = (idx / OW) % FH;
    int b  = idx / (OW * FH);
    float fx = ((float)ox + 0.5f) * (float)R - 0.5f;
    const float invR = 1.0f / (float)R;
    int xlo = max(0, (int)ceilf(fx - (float)R));
    int xhi = min(FW - 1, (int)floorf(fx + (float)R));
    const float* row = src + ((size_t)b * FH + y) * FW;
    float acc = 0.f, wxs = 0.f;
    for (int x = xlo; x <= xhi; x++) {
        float wx = fmaxf(0.f, 1.f - fabsf((float)x - fx) * invR);
        wxs += wx;
        acc += wx * row[x];
    }
    tmp[idx] = acc / wxs;
}

// Pass 2: vertical 512 -> OH at width OW, times `mul`.
template<int R, int OH, int OW>
__global__ void down_v(const float* __restrict__ tmp, float* __restrict__ dst,
                       float mul)
{
    int idx = blockIdx.x * 256 + threadIdx.x;   // 8*OH*OW
    int ox = idx % OW;
    int oy = (idx / OW) % OH;
    int b  = idx / (OW * OH);
    float fy = ((float)oy + 0.5f) * (float)R - 0.5f;
    const float invR = 1.0f / (float)R;
    int ylo = max(0, (int)ceilf(fy - (float)R));
    int yhi = min(FH - 1, (int)floorf(fy + (float)R));
    const float* col = tmp + (size_t)b * FH * OW + ox;
    float acc = 0.f, wys = 0.f;
    for (int y = ylo; y <= yhi; y++) {
        float wy = fmaxf(0.f, 1.f - fabsf((float)y - fy) * invR);
        wys += wy;
        acc += wy * col[(size_t)y * OW];
    }
    dst[idx] = acc / wys * mul;
}

// ---------------------------------------------------------------------------
// Launch
// ---------------------------------------------------------------------------
extern "C" void kernel_launch(void* const* d_in, const int* in_sizes, int n_in,
                              void* d_out, int out_size)
{
    (void)in_sizes; (void)n_in; (void)out_size;
    float* scr = nullptr;
    cudaGetSymbolAddress((void**)&scr, g_scratch);

    const float* fl0 = (const float*)d_in[0];
    const float* fr0 = (const float*)d_in[1];
    const float* fl1 = (const float*)d_in[2];
    const float* fr1 = (const float*)d_in[3];
    const float* fl2 = (const float*)d_in[4];
    const float* fr2 = (const float*)d_in[5];
    const float* w_in0  = (const float*)d_in[6];
    const float* w_mid0 = (const float*)d_in[7];
    const float* w_out0 = (const float*)d_in[8];
    const float* w_in1  = (const float*)d_in[9];
    const float* w_mid1 = (const float*)d_in[10];
    const float* w_out1 = (const float*)d_in[11];
    const float* w_in2  = (const float*)d_in[12];
    const float* w_mid2 = (const float*)d_in[13];
    const float* w_out2 = (const float*)d_in[14];

    // padded arena layout (floats)
    float* act0a  = scr + 0;          // 8*16*14*34*82 = 4,996,096
    float* act0b  = scr + 4996096;
    float* cost0p = scr + 9992192;    // 8*14*34*82    =   312,256
    float* cost0u = scr + 10304448;   // 8*12*32*80    =   245,760
    float* act1a  = scr + 10550208;   // 8*4*7*66*162  = 2,395,008
    float* act1b  = scr + 12945216;
    float* cost1p = scr + 15340224;   // 8*7*66*162    =   598,752
    float* cost1u = scr + 15938976;   // 8*5*64*160    =   409,600
    float* act2a  = scr + 16348576;   // 8*4*7*130*322 = 9,376,640
    float* act2b  = scr + 25725216;
    float* cost2p = scr + 35101856;   // 8*7*130*322   = 2,344,160
    float* cost2u = scr + 37446016;   // 8*5*128*320   = 1,638,400
    float* dd0    = scr + 39084416;   //   20,480
    float* dd1    = scr + 39104896;   //   81,920
    float* dd2    = scr + 39186816;   //  327,680
    float* wflow  = scr + 39514496;   //  327,680
    float* dtmp   = scr + 39842176;   // 8*512*320 = 1,310,720 (max of passes)

    float* out = (float*)d_out;
    const size_t NPX = (size_t)8 * 512 * 1280;
    float* pred0 = out;
    float* pred1 = out + NPX;
    float* pred2 = out + 2 * NPX;
    float* depth = out + 3 * NPX;

    // ---- scale 0 : D=12, H=32, W=80, 16 channels ----
    cost0_k<<<960, 256>>>(fl0, fr0, cost0p);
    conv3d_p<1, 16, 2, 12, 32, 80, true ><<<1920, 128>>>(cost0p, w_in0, act0a);
    conv3d_p<16, 16, 2, 12, 32, 80, true ><<<1920, 128>>>(act0a, w_mid0 + 0 * 6912, act0b);
    conv3d_p<16, 16, 2, 12, 32, 80, true ><<<1920, 128>>>(act0b, w_mid0 + 1 * 6912, act0a);
    conv3d_p<16, 16, 2, 12, 32, 80, true ><<<1920, 128>>>(act0a, w_mid0 + 2 * 6912, act0b);
    conv3d_p<16, 16, 2, 12, 32, 80, true ><<<1920, 128>>>(act0b, w_mid0 + 3 * 6912, act0a);
    conv3d_s<16, 12, 32, 80><<<960, 128>>>(act0a, w_out0, cost0u);
    dispreg_k<12, 0, 32, 80><<<80, 256>>>(cost0u, dd0, 16.0f);
    up_k<32, 80, false, true><<<5120, 256>>>(dd0, nullptr, pred0, depth);

    // ---- scale 1 : D=5, H=64, W=160, 4 channels ----
    down_h<8, 160><<<2560, 256>>>(pred0, dtmp);
    down_v<8, 64, 160><<<320, 256>>>(dtmp, wflow, 0.125f);
    costres_k<64, 160><<<1600, 256>>>(fl1, fr1, wflow, cost1p);
    conv3d_p<1, 4, 2, 5, 64, 160, true ><<<800, 128>>>(cost1p, w_in1, act1a);
    conv3d_p<4, 4, 2, 5, 64, 160, true ><<<800, 128>>>(act1a, w_mid1 + 0 * 432, act1b);
    conv3d_p<4, 4, 2, 5, 64, 160, true ><<<800, 128>>>(act1b, w_mid1 + 1 * 432, act1a);
    conv3d_p<4, 4, 2, 5, 64, 160, true ><<<800, 128>>>(act1a, w_mid1 + 2 * 432, act1b);
    conv3d_p<4, 4, 2, 5, 64, 160, true ><<<800, 128>>>(act1b, w_mid1 + 3 * 432, act1a);
    conv3d_s<4, 5, 64, 160><<<1600, 128>>>(act1a, w_out1, cost1u);
    dispreg_k<5, -2, 64, 160><<<320, 256>>>(cost1u, dd1, 8.0f);
    up_k<64, 160, true, false><<<5120, 256>>>(dd1, pred0, pred1, nullptr);

    // ---- scale 2 : D=5, H=128, W=320, 4 channels ----
    down_h<4, 320><<<5120, 256>>>(pred1, dtmp);
    down_v<4, 128, 320><<<1280, 256>>>(dtmp, wflow, 0.25f);
    costres_k<128, 320><<<6400, 256>>>(fl2, fr2, wflow, cost2p);
    conv3d_p<1, 4, 2, 5, 128, 320, true ><<<3200, 128>>>(cost2p, w_in2, act2a);
    conv3d_p<4, 4, 2, 5, 128, 320, true ><<<3200, 128>>>(act2a, w_mid2 + 0 * 432, act2b);
    conv3d_p<4, 4, 2, 5, 128, 320, true ><<<3200, 128>>>(act2b, w_mid2 + 1 * 432, act2a);
    conv3d_p<4, 4, 2, 5, 128, 320, true ><<<3200, 128>>>(act2a, w_mid2 + 2 * 432, act2b);
    conv3d_p<4, 4, 2, 5, 128, 320, true ><<<3200, 128>>>(act2b, w_mid2 + 3 * 432, act2a);
    conv3d_s<4, 5, 128, 320><<<6400, 128>>>(act2a, w_out2, cost2u);
    dispreg_k<5, -2, 128, 320><<<1280, 256>>>(cost2u, dd2, 4.0f);
    up_k<128, 320, true, false><<<5120, 256>>>(dd2, pred1, pred2, nullptr);
}

// round 9
// speedup vs baseline: 1.0722x; 1.0722x over previous
#include <cuda_runtime.h>
#include <cstdint>
#include <cstddef>
#include <math.h>

using ull = unsigned long long;
#define DEV_INLINE __device__ __forceinline__

DEV_INLINE void ffma2(ull &acc, ull a, ull w) {
    asm("fma.rn.f32x2 %0, %1, %2, %0;" : "+l"(acc) : "l"(a), "l"(w));
}
DEV_INLINE ull pack2(float lo, float hi) {
    ull r; asm("mov.b64 %0, {%1, %2};" : "=l"(r) : "f"(lo), "f"(hi)); return r;
}
DEV_INLINE void unpack2(ull v, float &lo, float &hi) {
    asm("mov.b64 {%0, %1}, %2;" : "=f"(lo), "=f"(hi) : "l"(v));
}
DEV_INLINE ull dup_lo(ull v) { float a, b; unpack2(v, a, b); return pack2(a, a); }
DEV_INLINE ull dup_hi(ull v) { float a, b; unpack2(v, a, b); return pack2(b, b); }

constexpr int FH = 512, FW = 1280;

// ---------------------------------------------------------------------------
// Scratch arena. Zero-initialized at module load; conv halos are NEVER written
// by any kernel, so they remain zero across all calls (deterministic).
// ---------------------------------------------------------------------------
__device__ float g_scratch[41000000];

// ---------------------------------------------------------------------------
// 3x3x3 SAME conv3d on ZERO-PADDED input [B,CIN,D+2,H+2,W+2], writes padded
// interior of out. ReLU optional. cout-pairs in f32x2 lanes, LDG.64 input
// loads, LDS.128 weights, double-buffered prefetch. launch_bounds(128,8)
// pins regs <= 64 -> 8 blocks/SM while keeping the prefetch distance.
// ---------------------------------------------------------------------------
template<int CIN, int COUT, int COP, int D, int H, int W, bool RELU>
__global__ void __launch_bounds__(128, 8) conv3d_p(
    const float* __restrict__ in, const float* __restrict__ wgt,
    float* __restrict__ out)
{
    constexpr int PW = W + 2, PH = H + 2, PD = D + 2;
    constexpr int PLANE = PH * PW;
    constexpr int CHS = PD * PLANE;
    constexpr int HP = H / 2, WP = W / 2;
    constexpr int SPB = 8 * D * HP * WP / 128;
    constexpr int NW = CIN * 27 * COP;

    __shared__ alignas(16) float2 ws[NW];
    const int g = blockIdx.x / SPB;
    const int co_base = g * 2 * COP;
    for (int i = threadIdx.x; i < NW; i += 128) {
        int cp  = i % COP;
        int pos = (i / COP) % 27;
        int ci  = i / (COP * 27);
        float2 wv;
        wv.x = wgt[((co_base + 2 * cp)     * CIN + ci) * 27 + pos];
        wv.y = wgt[((co_base + 2 * cp + 1) * CIN + ci) * 27 + pos];
        ws[(ci * 27 + pos) * COP + cp] = wv;
    }
    __syncthreads();

    int sidx = (blockIdx.x % SPB) * 128 + threadIdx.x;
    int wp = sidx % WP;
    int t  = sidx / WP;
    int hp = t % HP;
    t /= HP;
    int d = t % D;
    int b = t / D;
    int h0 = hp * 2, w0 = wp * 2;

    ull acc[4][COP];
    #pragma unroll
    for (int p = 0; p < 4; p++)
        #pragma unroll
        for (int c = 0; c < COP; c++) acc[p][c] = 0ULL;

    const float* base = in + (size_t)b * CIN * CHS
                           + (size_t)d * PLANE + (size_t)h0 * PW + w0;
    const ull* wsp = reinterpret_cast<const ull*>(ws);

    // patch rows are 8B-aligned (w0 even, PW even, all strides even)
    auto loadr = [&](ull dst[8], const float* q) {
        #pragma unroll
        for (int r = 0; r < 4; r++) {
            dst[2 * r]     = *reinterpret_cast<const ull*>(q + r * PW);
            dst[2 * r + 1] = *reinterpret_cast<const ull*>(q + r * PW + 2);
        }
    };
    auto addr = [&](int it) {
        return base + (size_t)(it / 3) * CHS + (size_t)(it % 3) * PLANE;
    };
    auto compute = [&](const ull buf[8], const ull* wt) {
        ull vp[4][4];
        #pragma unroll
        for (int r = 0; r < 4; r++) {
            vp[r][0] = dup_lo(buf[2 * r]);
            vp[r][1] = dup_hi(buf[2 * r]);
            vp[r][2] = dup_lo(buf[2 * r + 1]);
            vp[r][3] = dup_hi(buf[2 * r + 1]);
        }
        #pragma unroll
        for (int kh = 0; kh < 3; kh++) {
            #pragma unroll
            for (int kw = 0; kw < 3; kw++) {
                const ull* wkk = wt + (kh * 3 + kw) * COP;
                #pragma unroll
                for (int cp = 0; cp < COP; cp += 2) {
                    ulonglong2 wv = *reinterpret_cast<const ulonglong2*>(wkk + cp);
                    ffma2(acc[0][cp], vp[kh][kw],         wv.x);
                    ffma2(acc[1][cp], vp[kh][kw + 1],     wv.x);
                    ffma2(acc[2][cp], vp[kh + 1][kw],     wv.x);
                    ffma2(acc[3][cp], vp[kh + 1][kw + 1], wv.x);
                    ffma2(acc[0][cp + 1], vp[kh][kw],         wv.y);
                    ffma2(acc[1][cp + 1], vp[kh][kw + 1],     wv.y);
                    ffma2(acc[2][cp + 1], vp[kh + 1][kw],     wv.y);
                    ffma2(acc[3][cp + 1], vp[kh + 1][kw + 1], wv.y);
                }
            }
        }
    };

    ull bufA[8], bufB[8];
    loadr(bufA, addr(0));
    if constexpr (CIN == 1) {
        loadr(bufB, addr(1));
        compute(bufA, wsp);
        loadr(bufA, addr(2));
        compute(bufB, wsp + 9 * COP);
        compute(bufA, wsp + 18 * COP);
    } else {
        constexpr int NIT = 3 * CIN;
        #pragma unroll 1
        for (int it = 0; it < NIT; it += 2) {
            loadr(bufB, addr(it + 1));
            compute(bufA, wsp + it * 9 * COP);
            if (it + 2 < NIT) loadr(bufA, addr(it + 2));
            compute(bufB, wsp + (it + 1) * 9 * COP);
        }
    }

    size_t obase = ((size_t)(b * COUT) * PD + (d + 1)) * PLANE
                 + (size_t)(h0 + 1) * PW + (w0 + 1);
    #pragma unroll
    for (int cp = 0; cp < COP; cp++) {
        size_t o0 = obase + (size_t)(co_base + 2 * cp) * CHS;
        #pragma unroll
        for (int pp = 0; pp < 4; pp++) {
            float x, y;
            unpack2(acc[pp][cp], x, y);
            if (RELU) { x = fmaxf(x, 0.f); y = fmaxf(y, 0.f); }
            size_t o = o0 + (size_t)(pp >> 1) * PW + (pp & 1);
            out[o] = x;
            out[o + CHS] = y;
        }
    }
}

// ---------------------------------------------------------------------------
// Final conv: CIN -> 1 channel, padded input, UNPADDED output, no ReLU.
// 2x2 patch, double-buffered prefetch (R4 version).
// ---------------------------------------------------------------------------
template<int CIN, int D, int H, int W>
__global__ void __launch_bounds__(128) conv3d_s(
    const float* __restrict__ in, const float* __restrict__ wgt,
    float* __restrict__ out)
{
    constexpr int PW = W + 2, PH = H + 2, PD = D + 2;
    constexpr int PLANE = PH * PW;
    constexpr int CHS = PD * PLANE;
    constexpr int HP = H / 2, WP = W / 2;

    __shared__ float ws[CIN * 27];
    for (int i = threadIdx.x; i < CIN * 27; i += 128)
        ws[i] = wgt[i];
    __syncthreads();

    int sidx = blockIdx.x * 128 + threadIdx.x;
    int wp = sidx % WP;
    int t  = sidx / WP;
    int hp = t % HP;
    t /= HP;
    int d = t % D;
    int b = t / D;
    int h0 = hp * 2, w0 = wp * 2;

    float sacc[4] = {0.f, 0.f, 0.f, 0.f};
    const float* base = in + (size_t)b * CIN * CHS
                           + (size_t)d * PLANE + (size_t)h0 * PW + w0;

    auto loadr = [&](ull dst[8], const float* q) {
        #pragma unroll
        for (int r = 0; r < 4; r++) {
            dst[2 * r]     = *reinterpret_cast<const ull*>(q + r * PW);
            dst[2 * r + 1] = *reinterpret_cast<const ull*>(q + r * PW + 2);
        }
    };
    auto addr = [&](int it) {
        return base + (size_t)(it / 3) * CHS + (size_t)(it % 3) * PLANE;
    };
    auto compute = [&](const ull buf[8], const float* wt) {
        float v[4][4];
        #pragma unroll
        for (int r = 0; r < 4; r++) {
            unpack2(buf[2 * r],     v[r][0], v[r][1]);
            unpack2(buf[2 * r + 1], v[r][2], v[r][3]);
        }
        #pragma unroll
        for (int kh = 0; kh < 3; kh++) {
            #pragma unroll
            for (int kw = 0; kw < 3; kw++) {
                float wv = wt[kh * 3 + kw];
                sacc[0] = fmaf(v[kh][kw],         wv, sacc[0]);
                sacc[1] = fmaf(v[kh][kw + 1],     wv, sacc[1]);
                sacc[2] = fmaf(v[kh + 1][kw],     wv, sacc[2]);
                sacc[3] = fmaf(v[kh + 1][kw + 1], wv, sacc[3]);
            }
        }
    };

    ull bufA[8], bufB[8];
    loadr(bufA, addr(0));
    constexpr int NIT = 3 * CIN;
    #pragma unroll 1
    for (int it = 0; it < NIT; it += 2) {
        loadr(bufB, addr(it + 1));
        compute(bufA, ws + it * 9);
        if (it + 2 < NIT) loadr(bufA, addr(it + 2));
        compute(bufB, ws + (it + 1) * 9);
    }

    size_t bo = ((size_t)b * D + d) * (H * W) + (size_t)h0 * W + w0;
    out[bo]         = sacc[0];
    out[bo + 1]     = sacc[1];
    out[bo + W]     = sacc[2];
    out[bo + W + 1] = sacc[3];
}

// ---------------------------------------------------------------------------
// Scale-0 L1 cost volume -> PADDED cost buffer [B,1,14,34,82]
// ---------------------------------------------------------------------------
__global__ void cost0_k(const float* __restrict__ fl, const float* __restrict__ fr,
                        float* __restrict__ cost)
{
    int idx = blockIdx.x * 256 + threadIdx.x;   // 8*12*32*80
    int w  = idx % 80;
    int h  = (idx / 80) % 32;
    int dd = (idx / (80 * 32)) % 12;
    int b  = idx / (80 * 32 * 12);
    int src = w - dd;
    const float* flb = fl + (size_t)b * 8 * 32 * 80 + h * 80;
    const float* frb = fr + (size_t)b * 8 * 32 * 80 + h * 80;
    float s = 0.f;
    #pragma unroll
    for (int c = 0; c < 8; c++) {
        float a = flb[c * 32 * 80 + w];
        float r = (src >= 0) ? frb[c * 32 * 80 + src] : 0.f;
        s += fabsf(a - r);
    }
    cost[((size_t)b * 14 + dd + 1) * (34 * 82) + (h + 1) * 82 + (w + 1)] = s;
}

// ---------------------------------------------------------------------------
// Residual cost volume -> PADDED cost buffer [B,1,7,H+2,W+2].
// ONE thread per (b,h,w) computes ALL 5 shifts: since xs(s) differ by exactly
// 1, the fractional weight w1 is shared and the 5 bilinear windows form one
// 6-sample fr window per channel. fl loaded once (5x fewer loads overall).
// ---------------------------------------------------------------------------
template<int H, int W>
__global__ void costres_k(const float* __restrict__ fl, const float* __restrict__ fr,
                          const float* __restrict__ wflow, float* __restrict__ cost)
{
    constexpr int PW = W + 2, PH = H + 2;
    int idx = blockIdx.x * 256 + threadIdx.x;   // 8*H*W
    int w = idx % W;
    int h = (idx / W) % H;
    int b = idx / (W * H);

    float disp = wflow[((size_t)b * H + h) * W + w];
    // s = 0: xs = w - (disp - (-2)) = w - disp - 2; xs(s) = xs0 + s
    float xs0 = (float)w - disp - 2.0f;
    float x0f = floorf(xs0);
    float w1 = xs0 - x0f;          // shared across all 5 shifts
    int x0 = (int)x0f;

    bool inb[6];
    int ix[6];
    #pragma unroll
    for (int j = 0; j < 6; j++) {
        int xi = x0 + j;
        inb[j] = (xi >= 0) && (xi <= W - 1);
        ix[j]  = min(max(xi, 0), W - 1);
    }

    const float* flb = fl + ((size_t)b * 8 * H + h) * W;
    const float* frb = fr + ((size_t)b * 8 * H + h) * W;

    float costs[5] = {0.f, 0.f, 0.f, 0.f, 0.f};
    #pragma unroll
    for (int c = 0; c < 8; c++) {
        float a = flb[c * H * W + w];
        const float* frc = frb + c * H * W;
        float v[6];
        #pragma unroll
        for (int j = 0; j < 6; j++)
            v[j] = inb[j] ? frc[ix[j]] : 0.f;
        #pragma unroll
        for (int s = 0; s < 5; s++)
            costs[s] += fabsf(a - (v[s] * (1.f - w1) + v[s + 1] * w1));
    }

    size_t obase = ((size_t)b * 7 + 1) * (PH * PW) + (h + 1) * PW + (w + 1);
    #pragma unroll
    for (int s = 0; s < 5; s++)
        cost[obase + (size_t)s * (PH * PW)] = costs[s];
}

// ---------------------------------------------------------------------------
// Softargmin disparity regression (reads UNPADDED cost)
// ---------------------------------------------------------------------------
template<int DT, int START, int H, int W>
__global__ void dispreg_k(const float* __restrict__ cost, float* __restrict__ dout,
                          float scale)
{
    int idx = blockIdx.x * 256 + threadIdx.x;   // 8*H*W
    int w = idx % W;
    int h = (idx / W) % H;
    int b = idx / (W * H);
    float c[DT];
    #pragma unroll
    for (int i = 0; i < DT; i++)
        c[i] = cost[(((size_t)b * DT + i) * H + h) * W + w];
    float mn = c[0];
    #pragma unroll
    for (int i = 1; i < DT; i++) mn = fminf(mn, c[i]);
    float s = 0.f, num = 0.f;
    #pragma unroll
    for (int i = 0; i < DT; i++) {
        float p = expf(mn - c[i]);
        s += p;
        num += p * (float)(START + i);
    }
    dout[idx] = num / s * scale;
}

// ---------------------------------------------------------------------------
// Bilinear upsample to 512x1280 (jax half-pixel), 4 px/thread (float4 I/O),
// optional add of previous full-res pred, optional depth output.
// ---------------------------------------------------------------------------
template<int IH, int IW, bool ADD, bool DEPTH>
__global__ void up_k(const float* __restrict__ src, const float* __restrict__ addsrc,
                     float* __restrict__ outp, float* __restrict__ depthp)
{
    int idx = blockIdx.x * 256 + threadIdx.x;   // 8*512*320
    int oq = idx % (FW / 4);
    int oy = (idx / (FW / 4)) % FH;
    int b  = idx / ((FW / 4) * FH);

    float fy = ((float)oy + 0.5f) * ((float)IH / (float)FH) - 0.5f;
    fy = fminf(fmaxf(fy, 0.f), (float)(IH - 1));
    int y0 = (int)fy; float gy = fy - (float)y0; int y1 = min(y0 + 1, IH - 1);
    const float* sb = src + (size_t)b * IH * IW;
    const float* r0 = sb + y0 * IW;
    const float* r1 = sb + y1 * IW;

    size_t base = ((size_t)b * FH + oy) * FW + oq * 4;
    float4 res, dep;
    float* rp = reinterpret_cast<float*>(&res);
    float* dp = reinterpret_cast<float*>(&dep);
    #pragma unroll
    for (int j = 0; j < 4; j++) {
        int ox = oq * 4 + j;
        float fx = ((float)ox + 0.5f) * ((float)IW / (float)FW) - 0.5f;
        fx = fminf(fmaxf(fx, 0.f), (float)(IW - 1));
        int x0 = (int)fx; float gx = fx - (float)x0; int x1 = min(x0 + 1, IW - 1);
        float v = (r0[x0] * (1.f - gx) + r0[x1] * gx) * (1.f - gy)
                + (r1[x0] * (1.f - gx) + r1[x1] * gx) * gy;
        rp[j] = v;
    }
    if (ADD) {
        float4 a = *reinterpret_cast<const float4*>(addsrc + base);
        res.x += a.x; res.y += a.y; res.z += a.z; res.w += a.w;
    }
    *reinterpret_cast<float4*>(outp + base) = res;
    if (DEPTH) {
        #pragma unroll
        for (int j = 0; j < 4; j++)
            dp[j] = fminf(fmaxf(64.0f / fabsf(rp[j]), 0.1f), 100.0f);
        *reinterpret_cast<float4*>(depthp + base) = dep;
    }
}

// ---------------------------------------------------------------------------
// Separable antialiased downsample (jax triangle kernel, width R, per-axis
// normalized). Pass 1: horizontal 1280 -> OW at full height 512.
// ---------------------------------------------------------------------------
template<int R, int OW>
__global__ void down_h(const float* __restrict__ src, float* __restrict__ tmp)
{
    int idx = blockIdx.x * 256 + threadIdx.x;   // 8*512*OW
    int ox = idx % OW;
    int y  = (idx / OW) % FH;
    int b  = idx / (OW * FH);
    float fx = ((float)ox + 0.5f) * (float)R - 0.5f;
    const float invR = 1.0f / (float)R;
    int xlo = max(0, (int)ceilf(fx - (float)R));
    int xhi = min(FW - 1, (int)floorf(fx + (float)R));
    const float* row = src + ((size_t)b * FH + y) * FW;
    float acc = 0.f, wxs = 0.f;
    for (int x = xlo; x <= xhi; x++) {
        float wx = fmaxf(0.f, 1.f - fabsf((float)x - fx) * invR);
        wxs += wx;
        acc += wx * row[x];
    }
    tmp[idx] = acc / wxs;
}

// Pass 2: vertical 512 -> OH at width OW, times `mul`.
template<int R, int OH, int OW>
__global__ void down_v(const float* __restrict__ tmp, float* __restrict__ dst,
                       float mul)
{
    int idx = blockIdx.x * 256 + threadIdx.x;   // 8*OH*OW
    int ox = idx % OW;
    int oy = (idx / OW) % OH;
    int b  = idx / (OW * OH);
    float fy = ((float)oy + 0.5f) * (float)R - 0.5f;
    const float invR = 1.0f / (float)R;
    int ylo = max(0, (int)ceilf(fy - (float)R));
    int yhi = min(FH - 1, (int)floorf(fy + (float)R));
    const float* col = tmp + (size_t)b * FH * OW + ox;
    float acc = 0.f, wys = 0.f;
    for (int y = ylo; y <= yhi; y++) {
        float wy = fmaxf(0.f, 1.f - fabsf((float)y - fy) * invR);
        wys += wy;
        acc += wy * col[(size_t)y * OW];
    }
    dst[idx] = acc / wys * mul;
}

// ---------------------------------------------------------------------------
// Launch
// ---------------------------------------------------------------------------
extern "C" void kernel_launch(void* const* d_in, const int* in_sizes, int n_in,
                              void* d_out, int out_size)
{
    (void)in_sizes; (void)n_in; (void)out_size;
    float* scr = nullptr;
    cudaGetSymbolAddress((void**)&scr, g_scratch);

    const float* fl0 = (const float*)d_in[0];
    const float* fr0 = (const float*)d_in[1];
    const float* fl1 = (const float*)d_in[2];
    const float* fr1 = (const float*)d_in[3];
    const float* fl2 = (const float*)d_in[4];
    const float* fr2 = (const float*)d_in[5];
    const float* w_in0  = (const float*)d_in[6];
    const float* w_mid0 = (const float*)d_in[7];
    const float* w_out0 = (const float*)d_in[8];
    const float* w_in1  = (const float*)d_in[9];
    const float* w_mid1 = (const float*)d_in[10];
    const float* w_out1 = (const float*)d_in[11];
    const float* w_in2  = (const float*)d_in[12];
    const float* w_mid2 = (const float*)d_in[13];
    const float* w_out2 = (const float*)d_in[14];

    // padded arena layout (floats)
    float* act0a  = scr + 0;          // 8*16*14*34*82 = 4,996,096
    float* act0b  = scr + 4996096;
    float* cost0p = scr + 9992192;    // 8*14*34*82    =   312,256
    float* cost0u = scr + 10304448;   // 8*12*32*80    =   245,760
    float* act1a  = scr + 10550208;   // 8*4*7*66*162  = 2,395,008
    float* act1b  = scr + 12945216;
    float* cost1p = scr + 15340224;   // 8*7*66*162    =   598,752
    float* cost1u = scr + 15938976;   // 8*5*64*160    =   409,600
    float* act2a  = scr + 16348576;   // 8*4*7*130*322 = 9,376,640
    float* act2b  = scr + 25725216;
    float* cost2p = scr + 35101856;   // 8*7*130*322   = 2,344,160
    float* cost2u = scr + 37446016;   // 8*5*128*320   = 1,638,400
    float* dd0    = scr + 39084416;   //   20,480
    float* dd1    = scr + 39104896;   //   81,920
    float* dd2    = scr + 39186816;   //  327,680
    float* wflow  = scr + 39514496;   //  327,680
    float* dtmp   = scr + 39842176;   // 8*512*320 = 1,310,720 (max of passes)

    float* out = (float*)d_out;
    const size_t NPX = (size_t)8 * 512 * 1280;
    float* pred0 = out;
    float* pred1 = out + NPX;
    float* pred2 = out + 2 * NPX;
    float* depth = out + 3 * NPX;

    // ---- scale 0 : D=12, H=32, W=80, 16 channels ----
    cost0_k<<<960, 256>>>(fl0, fr0, cost0p);
    conv3d_p<1, 16, 2, 12, 32, 80, true ><<<1920, 128>>>(cost0p, w_in0, act0a);
    conv3d_p<16, 16, 2, 12, 32, 80, true ><<<1920, 128>>>(act0a, w_mid0 + 0 * 6912, act0b);
    conv3d_p<16, 16, 2, 12, 32, 80, true ><<<1920, 128>>>(act0b, w_mid0 + 1 * 6912, act0a);
    conv3d_p<16, 16, 2, 12, 32, 80, true ><<<1920, 128>>>(act0a, w_mid0 + 2 * 6912, act0b);
    conv3d_p<16, 16, 2, 12, 32, 80, true ><<<1920, 128>>>(act0b, w_mid0 + 3 * 6912, act0a);
    conv3d_s<16, 12, 32, 80><<<480, 128>>>(act0a, w_out0, cost0u);
    dispreg_k<12, 0, 32, 80><<<80, 256>>>(cost0u, dd0, 16.0f);
    up_k<32, 80, false, true><<<5120, 256>>>(dd0, nullptr, pred0, depth);

    // ---- scale 1 : D=5, H=64, W=160, 4 channels ----
    down_h<8, 160><<<2560, 256>>>(pred0, dtmp);
    down_v<8, 64, 160><<<320, 256>>>(dtmp, wflow, 0.125f);
    costres_k<64, 160><<<320, 256>>>(fl1, fr1, wflow, cost1p);
    conv3d_p<1, 4, 2, 5, 64, 160, true ><<<800, 128>>>(cost1p, w_in1, act1a);
    conv3d_p<4, 4, 2, 5, 64, 160, true ><<<800, 128>>>(act1a, w_mid1 + 0 * 432, act1b);
    conv3d_p<4, 4, 2, 5, 64, 160, true ><<<800, 128>>>(act1b, w_mid1 + 1 * 432, act1a);
    conv3d_p<4, 4, 2, 5, 64, 160, true ><<<800, 128>>>(act1a, w_mid1 + 2 * 432, act1b);
    conv3d_p<4, 4, 2, 5, 64, 160, true ><<<800, 128>>>(act1b, w_mid1 + 3 * 432, act1a);
    conv3d_s<4, 5, 64, 160><<<800, 128>>>(act1a, w_out1, cost1u);
    dispreg_k<5, -2, 64, 160><<<320, 256>>>(cost1u, dd1, 8.0f);
    up_k<64, 160, true, false><<<5120, 256>>>(dd1, pred0, pred1, nullptr);

    // ---- scale 2 : D=5, H=128, W=320, 4 channels ----
    down_h<4, 320><<<5120, 256>>>(pred1, dtmp);
    down_v<4, 128, 320><<<1280, 256>>>(dtmp, wflow, 0.25f);
    costres_k<128, 320><<<1280, 256>>>(fl2, fr2, wflow, cost2p);
    conv3d_p<1, 4, 2, 5, 128, 320, true ><<<3200, 128>>>(cost2p, w_in2, act2a);
    conv3d_p<4, 4, 2, 5, 128, 320, true ><<<3200, 128>>>(act2a, w_mid2 + 0 * 432, act2b);
    conv3d_p<4, 4, 2, 5, 128, 320, true ><<<3200, 128>>>(act2b, w_mid2 + 1 * 432, act2a);
    conv3d_p<4, 4, 2, 5, 128, 320, true ><<<3200, 128>>>(act2a, w_mid2 + 2 * 432, act2b);
    conv3d_p<4, 4, 2, 5, 128, 320, true ><<<3200, 128>>>(act2b, w_mid2 + 3 * 432, act2a);
    conv3d_s<4, 5, 128, 320><<<3200, 128>>>(act2a, w_out2, cost2u);
    dispreg_k<5, -2, 128, 320><<<1280, 256>>>(cost2u, dd2, 4.0f);
    up_k<128, 320, true, false><<<5120, 256>>>(dd2, pred1, pred2, nullptr);
}

// round 10
// speedup vs baseline: 1.1002x; 1.0261x over previous
#include <cuda_runtime.h>
#include <cstdint>
#include <cstddef>
#include <math.h>

using ull = unsigned long long;
#define DEV_INLINE __device__ __forceinline__

DEV_INLINE void ffma2(ull &acc, ull a, ull w) {
    asm("fma.rn.f32x2 %0, %1, %2, %0;" : "+l"(acc) : "l"(a), "l"(w));
}
DEV_INLINE ull pack2(float lo, float hi) {
    ull r; asm("mov.b64 %0, {%1, %2};" : "=l"(r) : "f"(lo), "f"(hi)); return r;
}
DEV_INLINE void unpack2(ull v, float &lo, float &hi) {
    asm("mov.b64 {%0, %1}, %2;" : "=f"(lo), "=f"(hi) : "l"(v));
}
DEV_INLINE ull dup_lo(ull v) { float a, b; unpack2(v, a, b); return pack2(a, a); }
DEV_INLINE ull dup_hi(ull v) { float a, b; unpack2(v, a, b); return pack2(b, b); }

constexpr int FH = 512, FW = 1280;

// ---------------------------------------------------------------------------
// Scratch arena. Zero-initialized at module load; conv halos are NEVER written
// by any kernel, so they remain zero across all calls (deterministic).
// ---------------------------------------------------------------------------
__device__ float g_scratch[41000000];

// ---------------------------------------------------------------------------
// 3x3x3 SAME conv3d on ZERO-PADDED input [B,CIN,D+2,H+2,W+2], writes padded
// interior of out. ReLU optional. cout-pairs in f32x2 lanes, LDG.64 input
// loads, LDS.128 weights, double-buffered prefetch (R4 configuration — the
// measured local optimum: COP=2, no reg cap, distance-1 prefetch).
// ---------------------------------------------------------------------------
template<int CIN, int COUT, int COP, int D, int H, int W, bool RELU>
__global__ void __launch_bounds__(128) conv3d_p(
    const float* __restrict__ in, const float* __restrict__ wgt,
    float* __restrict__ out)
{
    constexpr int PW = W + 2, PH = H + 2, PD = D + 2;
    constexpr int PLANE = PH * PW;
    constexpr int CHS = PD * PLANE;
    constexpr int HP = H / 2, WP = W / 2;
    constexpr int SPB = 8 * D * HP * WP / 128;
    constexpr int NW = CIN * 27 * COP;

    __shared__ alignas(16) float2 ws[NW];
    const int g = blockIdx.x / SPB;
    const int co_base = g * 2 * COP;
    for (int i = threadIdx.x; i < NW; i += 128) {
        int cp  = i % COP;
        int pos = (i / COP) % 27;
        int ci  = i / (COP * 27);
        float2 wv;
        wv.x = wgt[((co_base + 2 * cp)     * CIN + ci) * 27 + pos];
        wv.y = wgt[((co_base + 2 * cp + 1) * CIN + ci) * 27 + pos];
        ws[(ci * 27 + pos) * COP + cp] = wv;
    }
    __syncthreads();

    int sidx = (blockIdx.x % SPB) * 128 + threadIdx.x;
    int wp = sidx % WP;
    int t  = sidx / WP;
    int hp = t % HP;
    t /= HP;
    int d = t % D;
    int b = t / D;
    int h0 = hp * 2, w0 = wp * 2;

    ull acc[4][COP];
    #pragma unroll
    for (int p = 0; p < 4; p++)
        #pragma unroll
        for (int c = 0; c < COP; c++) acc[p][c] = 0ULL;

    const float* base = in + (size_t)b * CIN * CHS
                           + (size_t)d * PLANE + (size_t)h0 * PW + w0;
    const ull* wsp = reinterpret_cast<const ull*>(ws);

    // patch rows are 8B-aligned (w0 even, PW even, all strides even)
    auto loadr = [&](ull dst[8], const float* q) {
        #pragma unroll
        for (int r = 0; r < 4; r++) {
            dst[2 * r]     = *reinterpret_cast<const ull*>(q + r * PW);
            dst[2 * r + 1] = *reinterpret_cast<const ull*>(q + r * PW + 2);
        }
    };
    auto addr = [&](int it) {
        return base + (size_t)(it / 3) * CHS + (size_t)(it % 3) * PLANE;
    };
    auto compute = [&](const ull buf[8], const ull* wt) {
        ull vp[4][4];
        #pragma unroll
        for (int r = 0; r < 4; r++) {
            vp[r][0] = dup_lo(buf[2 * r]);
            vp[r][1] = dup_hi(buf[2 * r]);
            vp[r][2] = dup_lo(buf[2 * r + 1]);
            vp[r][3] = dup_hi(buf[2 * r + 1]);
        }
        #pragma unroll
        for (int kh = 0; kh < 3; kh++) {
            #pragma unroll
            for (int kw = 0; kw < 3; kw++) {
                const ull* wkk = wt + (kh * 3 + kw) * COP;
                #pragma unroll
                for (int cp = 0; cp < COP; cp += 2) {
                    ulonglong2 wv = *reinterpret_cast<const ulonglong2*>(wkk + cp);
                    ffma2(acc[0][cp], vp[kh][kw],         wv.x);
                    ffma2(acc[1][cp], vp[kh][kw + 1],     wv.x);
                    ffma2(acc[2][cp], vp[kh + 1][kw],     wv.x);
                    ffma2(acc[3][cp], vp[kh + 1][kw + 1], wv.x);
                    ffma2(acc[0][cp + 1], vp[kh][kw],         wv.y);
                    ffma2(acc[1][cp + 1], vp[kh][kw + 1],     wv.y);
                    ffma2(acc[2][cp + 1], vp[kh + 1][kw],     wv.y);
                    ffma2(acc[3][cp + 1], vp[kh + 1][kw + 1], wv.y);
                }
            }
        }
    };

    ull bufA[8], bufB[8];
    loadr(bufA, addr(0));
    if constexpr (CIN == 1) {
        loadr(bufB, addr(1));
        compute(bufA, wsp);
        loadr(bufA, addr(2));
        compute(bufB, wsp + 9 * COP);
        compute(bufA, wsp + 18 * COP);
    } else {
        constexpr int NIT = 3 * CIN;
        #pragma unroll 1
        for (int it = 0; it < NIT; it += 2) {
            loadr(bufB, addr(it + 1));
            compute(bufA, wsp + it * 9 * COP);
            if (it + 2 < NIT) loadr(bufA, addr(it + 2));
            compute(bufB, wsp + (it + 1) * 9 * COP);
        }
    }

    size_t obase = ((size_t)(b * COUT) * PD + (d + 1)) * PLANE
                 + (size_t)(h0 + 1) * PW + (w0 + 1);
    #pragma unroll
    for (int cp = 0; cp < COP; cp++) {
        size_t o0 = obase + (size_t)(co_base + 2 * cp) * CHS;
        #pragma unroll
        for (int pp = 0; pp < 4; pp++) {
            float x, y;
            unpack2(acc[pp][cp], x, y);
            if (RELU) { x = fmaxf(x, 0.f); y = fmaxf(y, 0.f); }
            size_t o = o0 + (size_t)(pp >> 1) * PW + (pp & 1);
            out[o] = x;
            out[o + CHS] = y;
        }
    }
}

// ---------------------------------------------------------------------------
// Final conv: CIN -> 1 channel, padded input, UNPADDED output, no ReLU.
// 2x2 patch, double-buffered prefetch (R4 version).
// ---------------------------------------------------------------------------
template<int CIN, int D, int H, int W>
__global__ void __launch_bounds__(128) conv3d_s(
    const float* __restrict__ in, const float* __restrict__ wgt,
    float* __restrict__ out)
{
    constexpr int PW = W + 2, PH = H + 2, PD = D + 2;
    constexpr int PLANE = PH * PW;
    constexpr int CHS = PD * PLANE;
    constexpr int HP = H / 2, WP = W / 2;

    __shared__ float ws[CIN * 27];
    for (int i = threadIdx.x; i < CIN * 27; i += 128)
        ws[i] = wgt[i];
    __syncthreads();

    int sidx = blockIdx.x * 128 + threadIdx.x;
    int wp = sidx % WP;
    int t  = sidx / WP;
    int hp = t % HP;
    t /= HP;
    int d = t % D;
    int b = t / D;
    int h0 = hp * 2, w0 = wp * 2;

    float sacc[4] = {0.f, 0.f, 0.f, 0.f};
    const float* base = in + (size_t)b * CIN * CHS
                           + (size_t)d * PLANE + (size_t)h0 * PW + w0;

    auto loadr = [&](ull dst[8], const float* q) {
        #pragma unroll
        for (int r = 0; r < 4; r++) {
            dst[2 * r]     = *reinterpret_cast<const ull*>(q + r * PW);
            dst[2 * r + 1] = *reinterpret_cast<const ull*>(q + r * PW + 2);
        }
    };
    auto addr = [&](int it) {
        return base + (size_t)(it / 3) * CHS + (size_t)(it % 3) * PLANE;
    };
    auto compute = [&](const ull buf[8], const float* wt) {
        float v[4][4];
        #pragma unroll
        for (int r = 0; r < 4; r++) {
            unpack2(buf[2 * r],     v[r][0], v[r][1]);
            unpack2(buf[2 * r + 1], v[r][2], v[r][3]);
        }
        #pragma unroll
        for (int kh = 0; kh < 3; kh++) {
            #pragma unroll
            for (int kw = 0; kw < 3; kw++) {
                float wv = wt[kh * 3 + kw];
                sacc[0] = fmaf(v[kh][kw],         wv, sacc[0]);
                sacc[1] = fmaf(v[kh][kw + 1],     wv, sacc[1]);
                sacc[2] = fmaf(v[kh + 1][kw],     wv, sacc[2]);
                sacc[3] = fmaf(v[kh + 1][kw + 1], wv, sacc[3]);
            }
        }
    };

    ull bufA[8], bufB[8];
    loadr(bufA, addr(0));
    constexpr int NIT = 3 * CIN;
    #pragma unroll 1
    for (int it = 0; it < NIT; it += 2) {
        loadr(bufB, addr(it + 1));
        compute(bufA, ws + it * 9);
        if (it + 2 < NIT) loadr(bufA, addr(it + 2));
        compute(bufB, ws + (it + 1) * 9);
    }

    size_t bo = ((size_t)b * D + d) * (H * W) + (size_t)h0 * W + w0;
    out[bo]         = sacc[0];
    out[bo + 1]     = sacc[1];
    out[bo + W]     = sacc[2];
    out[bo + W + 1] = sacc[3];
}

// ---------------------------------------------------------------------------
// Scale-0 L1 cost volume -> PADDED cost buffer [B,1,14,34,82]
// ---------------------------------------------------------------------------
__global__ void cost0_k(const float* __restrict__ fl, const float* __restrict__ fr,
                        float* __restrict__ cost)
{
    int idx = blockIdx.x * 256 + threadIdx.x;   // 8*12*32*80
    int w  = idx % 80;
    int h  = (idx / 80) % 32;
    int dd = (idx / (80 * 32)) % 12;
    int b  = idx / (80 * 32 * 12);
    int src = w - dd;
    const float* flb = fl + (size_t)b * 8 * 32 * 80 + h * 80;
    const float* frb = fr + (size_t)b * 8 * 32 * 80 + h * 80;
    float s = 0.f;
    #pragma unroll
    for (int c = 0; c < 8; c++) {
        float a = flb[c * 32 * 80 + w];
        float r = (src >= 0) ? frb[c * 32 * 80 + src] : 0.f;
        s += fabsf(a - r);
    }
    cost[((size_t)b * 14 + dd + 1) * (34 * 82) + (h + 1) * 82 + (w + 1)] = s;
}

// ---------------------------------------------------------------------------
// Residual cost volume -> PADDED cost buffer [B,1,7,H+2,W+2].
// ONE thread per (b,h,w) computes ALL 5 shifts: xs(s) differ by exactly 1,
// so the fractional weight w1 is shared and the 5 bilinear windows form one
// 6-sample fr window per channel (fl loaded once; ~5x fewer loads).
// ---------------------------------------------------------------------------
template<int H, int W>
__global__ void costres_k(const float* __restrict__ fl, const float* __restrict__ fr,
                          const float* __restrict__ wflow, float* __restrict__ cost)
{
    constexpr int PW = W + 2, PH = H + 2;
    int idx = blockIdx.x * 256 + threadIdx.x;   // 8*H*W
    int w = idx % W;
    int h = (idx / W) % H;
    int b = idx / (W * H);

    float disp = wflow[((size_t)b * H + h) * W + w];
    // s = 0: xs = w - (disp - (-2)) = w - disp - 2; xs(s) = xs0 + s
    float xs0 = (float)w - disp - 2.0f;
    float x0f = floorf(xs0);
    float w1 = xs0 - x0f;          // shared across all 5 shifts
    int x0 = (int)x0f;

    bool inb[6];
    int ix[6];
    #pragma unroll
    for (int j = 0; j < 6; j++) {
        int xi = x0 + j;
        inb[j] = (xi >= 0) && (xi <= W - 1);
        ix[j]  = min(max(xi, 0), W - 1);
    }

    const float* flb = fl + ((size_t)b * 8 * H + h) * W;
    const float* frb = fr + ((size_t)b * 8 * H + h) * W;

    float costs[5] = {0.f, 0.f, 0.f, 0.f, 0.f};
    #pragma unroll
    for (int c = 0; c < 8; c++) {
        float a = flb[c * H * W + w];
        const float* frc = frb + c * H * W;
        float v[6];
        #pragma unroll
        for (int j = 0; j < 6; j++)
            v[j] = inb[j] ? frc[ix[j]] : 0.f;
        #pragma unroll
        for (int s = 0; s < 5; s++)
            costs[s] += fabsf(a - (v[s] * (1.f - w1) + v[s + 1] * w1));
    }

    size_t obase = ((size_t)b * 7 + 1) * (PH * PW) + (h + 1) * PW + (w + 1);
    #pragma unroll
    for (int s = 0; s < 5; s++)
        cost[obase + (size_t)s * (PH * PW)] = costs[s];
}

// ---------------------------------------------------------------------------
// Softargmin disparity regression (reads UNPADDED cost)
// ---------------------------------------------------------------------------
template<int DT, int START, int H, int W>
__global__ void dispreg_k(const float* __restrict__ cost, float* __restrict__ dout,
                          float scale)
{
    int idx = blockIdx.x * 256 + threadIdx.x;   // 8*H*W
    int w = idx % W;
    int h = (idx / W) % H;
    int b = idx / (W * H);
    float c[DT];
    #pragma unroll
    for (int i = 0; i < DT; i++)
        c[i] = cost[(((size_t)b * DT + i) * H + h) * W + w];
    float mn = c[0];
    #pragma unroll
    for (int i = 1; i < DT; i++) mn = fminf(mn, c[i]);
    float s = 0.f, num = 0.f;
    #pragma unroll
    for (int i = 0; i < DT; i++) {
        float p = expf(mn - c[i]);
        s += p;
        num += p * (float)(START + i);
    }
    dout[idx] = num / s * scale;
}

// ---------------------------------------------------------------------------
// Bilinear upsample to 512x1280 (jax half-pixel), 4 px/thread (float4 I/O),
// optional add of previous full-res pred, optional depth output.
// ---------------------------------------------------------------------------
template<int IH, int IW, bool ADD, bool DEPTH>
__global__ void up_k(const float* __restrict__ src, const float* __restrict__ addsrc,
                     float* __restrict__ outp, float* __restrict__ depthp)
{
    int idx = blockIdx.x * 256 + threadIdx.x;   // 8*512*320
    int oq = idx % (FW / 4);
    int oy = (idx / (FW / 4)) % FH;
    int b  = idx / ((FW / 4) * FH);

    float fy = ((float)oy + 0.5f) * ((float)IH / (float)FH) - 0.5f;
    fy = fminf(fmaxf(fy, 0.f), (float)(IH - 1));
    int y0 = (int)fy; float gy = fy - (float)y0; int y1 = min(y0 + 1, IH - 1);
    const float* sb = src + (size_t)b * IH * IW;
    const float* r0 = sb + y0 * IW;
    const float* r1 = sb + y1 * IW;

    size_t base = ((size_t)b * FH + oy) * FW + oq * 4;
    float4 res, dep;
    float* rp = reinterpret_cast<float*>(&res);
    float* dp = reinterpret_cast<float*>(&dep);
    #pragma unroll
    for (int j = 0; j < 4; j++) {
        int ox = oq * 4 + j;
        float fx = ((float)ox + 0.5f) * ((float)IW / (float)FW) - 0.5f;
        fx = fminf(fmaxf(fx, 0.f), (float)(IW - 1));
        int x0 = (int)fx; float gx = fx - (float)x0; int x1 = min(x0 + 1, IW - 1);
        float v = (r0[x0] * (1.f - gx) + r0[x1] * gx) * (1.f - gy)
                + (r1[x0] * (1.f - gx) + r1[x1] * gx) * gy;
        rp[j] = v;
    }
    if (ADD) {
        float4 a = *reinterpret_cast<const float4*>(addsrc + base);
        res.x += a.x; res.y += a.y; res.z += a.z; res.w += a.w;
    }
    *reinterpret_cast<float4*>(outp + base) = res;
    if (DEPTH) {
        #pragma unroll
        for (int j = 0; j < 4; j++)
            dp[j] = fminf(fmaxf(64.0f / fabsf(rp[j]), 0.1f), 100.0f);
        *reinterpret_cast<float4*>(depthp + base) = dep;
    }
}

// ---------------------------------------------------------------------------
// Separable antialiased downsample (jax triangle kernel, width R, per-axis
// normalized). Pass 1: horizontal 1280 -> OW at full height 512.
// ---------------------------------------------------------------------------
template<int R, int OW>
__global__ void down_h(const float* __restrict__ src, float* __restrict__ tmp)
{
    int idx = blockIdx.x * 256 + threadIdx.x;   // 8*512*OW
    int ox = idx % OW;
    int y  = (idx / OW) % FH;
    int b  = idx / (OW * FH);
    float fx = ((float)ox + 0.5f) * (float)R - 0.5f;
    const float invR = 1.0f / (float)R;
    int xlo = max(0, (int)ceilf(fx - (float)R));
    int xhi = min(FW - 1, (int)floorf(fx + (float)R));
    const float* row = src + ((size_t)b * FH + y) * FW;
    float acc = 0.f, wxs = 0.f;
    for (int x = xlo; x <= xhi; x++) {
        float wx = fmaxf(0.f, 1.f - fabsf((float)x - fx) * invR);
        wxs += wx;
        acc += wx * row[x];
    }
    tmp[idx] = acc / wxs;
}

// Pass 2: vertical 512 -> OH at width OW, times `mul`.
template<int R, int OH, int OW>
__global__ void down_v(const float* __restrict__ tmp, float* __restrict__ dst,
                       float mul)
{
    int idx = blockIdx.x * 256 + threadIdx.x;   // 8*OH*OW
    int ox = idx % OW;
    int oy = (idx / OW) % OH;
    int b  = idx / (OW * OH);
    float fy = ((float)oy + 0.5f) * (float)R - 0.5f;
    const float invR = 1.0f / (float)R;
    int ylo = max(0, (int)ceilf(fy - (float)R));
    int yhi = min(FH - 1, (int)floorf(fy + (float)R));
    const float* col = tmp + (size_t)b * FH * OW + ox;
    float acc = 0.f, wys = 0.f;
    for (int y = ylo; y <= yhi; y++) {
        float wy = fmaxf(0.f, 1.f - fabsf((float)y - fy) * invR);
        wys += wy;
        acc += wy * col[(size_t)y * OW];
    }
    dst[idx] = acc / wys * mul;
}

// ---------------------------------------------------------------------------
// Launch
// ---------------------------------------------------------------------------
extern "C" void kernel_launch(void* const* d_in, const int* in_sizes, int n_in,
                              void* d_out, int out_size)
{
    (void)in_sizes; (void)n_in; (void)out_size;
    float* scr = nullptr;
    cudaGetSymbolAddress((void**)&scr, g_scratch);

    const float* fl0 = (const float*)d_in[0];
    const float* fr0 = (const float*)d_in[1];
    const float* fl1 = (const float*)d_in[2];
    const float* fr1 = (const float*)d_in[3];
    const float* fl2 = (const float*)d_in[4];
    const float* fr2 = (const float*)d_in[5];
    const float* w_in0  = (const float*)d_in[6];
    const float* w_mid0 = (const float*)d_in[7];
    const float* w_out0 = (const float*)d_in[8];
    const float* w_in1  = (const float*)d_in[9];
    const float* w_mid1 = (const float*)d_in[10];
    const float* w_out1 = (const float*)d_in[11];
    const float* w_in2  = (const float*)d_in[12];
    const float* w_mid2 = (const float*)d_in[13];
    const float* w_out2 = (const float*)d_in[14];

    // padded arena layout (floats)
    float* act0a  = scr + 0;          // 8*16*14*34*82 = 4,996,096
    float* act0b  = scr + 4996096;
    float* cost0p = scr + 9992192;    // 8*14*34*82    =   312,256
    float* cost0u = scr + 10304448;   // 8*12*32*80    =   245,760
    float* act1a  = scr + 10550208;   // 8*4*7*66*162  = 2,395,008
    float* act1b  = scr + 12945216;
    float* cost1p = scr + 15340224;   // 8*7*66*162    =   598,752
    float* cost1u = scr + 15938976;   // 8*5*64*160    =   409,600
    float* act2a  = scr + 16348576;   // 8*4*7*130*322 = 9,376,640
    float* act2b  = scr + 25725216;
    float* cost2p = scr + 35101856;   // 8*7*130*322   = 2,344,160
    float* cost2u = scr + 37446016;   // 8*5*128*320   = 1,638,400
    float* dd0    = scr + 39084416;   //   20,480
    float* dd1    = scr + 39104896;   //   81,920
    float* dd2    = scr + 39186816;   //  327,680
    float* wflow  = scr + 39514496;   //  327,680
    float* dtmp   = scr + 39842176;   // 8*512*320 = 1,310,720 (max of passes)

    float* out = (float*)d_out;
    const size_t NPX = (size_t)8 * 512 * 1280;
    float* pred0 = out;
    float* pred1 = out + NPX;
    float* pred2 = out + 2 * NPX;
    float* depth = out + 3 * NPX;

    // ---- scale 0 : D=12, H=32, W=80, 16 channels ----
    cost0_k<<<960, 256>>>(fl0, fr0, cost0p);
    conv3d_p<1, 16, 2, 12, 32, 80, true ><<<1920, 128>>>(cost0p, w_in0, act0a);
    conv3d_p<16, 16, 2, 12, 32, 80, true ><<<1920, 128>>>(act0a, w_mid0 + 0 * 6912, act0b);
    conv3d_p<16, 16, 2, 12, 32, 80, true ><<<1920, 128>>>(act0b, w_mid0 + 1 * 6912, act0a);
    conv3d_p<16, 16, 2, 12, 32, 80, true ><<<1920, 128>>>(act0a, w_mid0 + 2 * 6912, act0b);
    conv3d_p<16, 16, 2, 12, 32, 80, true ><<<1920, 128>>>(act0b, w_mid0 + 3 * 6912, act0a);
    conv3d_s<16, 12, 32, 80><<<480, 128>>>(act0a, w_out0, cost0u);
    dispreg_k<12, 0, 32, 80><<<80, 256>>>(cost0u, dd0, 16.0f);
    up_k<32, 80, false, true><<<5120, 256>>>(dd0, nullptr, pred0, depth);

    // ---- scale 1 : D=5, H=64, W=160, 4 channels ----
    down_h<8, 160><<<2560, 256>>>(pred0, dtmp);
    down_v<8, 64, 160><<<320, 256>>>(dtmp, wflow, 0.125f);
    costres_k<64, 160><<<320, 256>>>(fl1, fr1, wflow, cost1p);
    conv3d_p<1, 4, 2, 5, 64, 160, true ><<<800, 128>>>(cost1p, w_in1, act1a);
    conv3d_p<4, 4, 2, 5, 64, 160, true ><<<800, 128>>>(act1a, w_mid1 + 0 * 432, act1b);
    conv3d_p<4, 4, 2, 5, 64, 160, true ><<<800, 128>>>(act1b, w_mid1 + 1 * 432, act1a);
    conv3d_p<4, 4, 2, 5, 64, 160, true ><<<800, 128>>>(act1a, w_mid1 + 2 * 432, act1b);
    conv3d_p<4, 4, 2, 5, 64, 160, true ><<<800, 128>>>(act1b, w_mid1 + 3 * 432, act1a);
    conv3d_s<4, 5, 64, 160><<<800, 128>>>(act1a, w_out1, cost1u);
    dispreg_k<5, -2, 64, 160><<<320, 256>>>(cost1u, dd1, 8.0f);
    up_k<64, 160, true, false><<<5120, 256>>>(dd1, pred0, pred1, nullptr);

    // ---- scale 2 : D=5, H=128, W=320, 4 channels ----
    down_h<4, 320><<<5120, 256>>>(pred1, dtmp);
    down_v<4, 128, 320><<<1280, 256>>>(dtmp, wflow, 0.25f);
    costres_k<128, 320><<<1280, 256>>>(fl2, fr2, wflow, cost2p);
    conv3d_p<1, 4, 2, 5, 128, 320, true ><<<3200, 128>>>(cost2p, w_in2, act2a);
    conv3d_p<4, 4, 2, 5, 128, 320, true ><<<3200, 128>>>(act2a, w_mid2 + 0 * 432, act2b);
    conv3d_p<4, 4, 2, 5, 128, 320, true ><<<3200, 128>>>(act2b, w_mid2 + 1 * 432, act2a);
    conv3d_p<4, 4, 2, 5, 128, 320, true ><<<3200, 128>>>(act2a, w_mid2 + 2 * 432, act2b);
    conv3d_p<4, 4, 2, 5, 128, 320, true ><<<3200, 128>>>(act2b, w_mid2 + 3 * 432, act2a);
    conv3d_s<4, 5, 128, 320><<<3200, 128>>>(act2a, w_out2, cost2u);
    dispreg_k<5, -2, 128, 320><<<1280, 256>>>(cost2u, dd2, 4.0f);
    up_k<128, 320, true, false><<<5120, 256>>>(dd2, pred1, pred2, nullptr);
}

// round 11
// speedup vs baseline: 1.1160x; 1.0143x over previous
#include <cuda_runtime.h>
#include <cstdint>
#include <cstddef>
#include <math.h>

using ull = unsigned long long;
#define DEV_INLINE __device__ __forceinline__

DEV_INLINE void ffma2(ull &acc, ull a, ull w) {
    asm("fma.rn.f32x2 %0, %1, %2, %0;" : "+l"(acc) : "l"(a), "l"(w));
}
DEV_INLINE ull pack2(float lo, float hi) {
    ull r; asm("mov.b64 %0, {%1, %2};" : "=l"(r) : "f"(lo), "f"(hi)); return r;
}
DEV_INLINE void unpack2(ull v, float &lo, float &hi) {
    asm("mov.b64 {%0, %1}, %2;" : "=f"(lo), "=f"(hi) : "l"(v));
}
DEV_INLINE ull dup_lo(ull v) { float a, b; unpack2(v, a, b); return pack2(a, a); }
DEV_INLINE ull dup_hi(ull v) { float a, b; unpack2(v, a, b); return pack2(b, b); }

constexpr int FH = 512, FW = 1280;

// ---------------------------------------------------------------------------
// Scratch arena. Zero-initialized at module load; conv halos are NEVER written
// by any kernel, so they remain zero across all calls (deterministic).
// ---------------------------------------------------------------------------
__device__ float g_scratch[41000000];

// ---------------------------------------------------------------------------
// 3x3x3 SAME conv3d on ZERO-PADDED input [B,CIN,D+2,H+2,W+2], writes padded
// interior of out. ReLU optional. cout-pairs in f32x2 lanes, LDG.64 input
// loads, LDS.128 weights, double-buffered prefetch (R4 configuration — the
// measured local optimum: COP=2, no reg cap, distance-1 prefetch).
// ---------------------------------------------------------------------------
template<int CIN, int COUT, int COP, int D, int H, int W, bool RELU>
__global__ void __launch_bounds__(128) conv3d_p(
    const float* __restrict__ in, const float* __restrict__ wgt,
    float* __restrict__ out)
{
    constexpr int PW = W + 2, PH = H + 2, PD = D + 2;
    constexpr int PLANE = PH * PW;
    constexpr int CHS = PD * PLANE;
    constexpr int HP = H / 2, WP = W / 2;
    constexpr int SPB = 8 * D * HP * WP / 128;
    constexpr int NW = CIN * 27 * COP;

    __shared__ alignas(16) float2 ws[NW];
    const int g = blockIdx.x / SPB;
    const int co_base = g * 2 * COP;
    for (int i = threadIdx.x; i < NW; i += 128) {
        int cp  = i % COP;
        int pos = (i / COP) % 27;
        int ci  = i / (COP * 27);
        float2 wv;
        wv.x = wgt[((co_base + 2 * cp)     * CIN + ci) * 27 + pos];
        wv.y = wgt[((co_base + 2 * cp + 1) * CIN + ci) * 27 + pos];
        ws[(ci * 27 + pos) * COP + cp] = wv;
    }
    __syncthreads();

    int sidx = (blockIdx.x % SPB) * 128 + threadIdx.x;
    int wp = sidx % WP;
    int t  = sidx / WP;
    int hp = t % HP;
    t /= HP;
    int d = t % D;
    int b = t / D;
    int h0 = hp * 2, w0 = wp * 2;

    ull acc[4][COP];
    #pragma unroll
    for (int p = 0; p < 4; p++)
        #pragma unroll
        for (int c = 0; c < COP; c++) acc[p][c] = 0ULL;

    const float* base = in + (size_t)b * CIN * CHS
                           + (size_t)d * PLANE + (size_t)h0 * PW + w0;
    const ull* wsp = reinterpret_cast<const ull*>(ws);

    // patch rows are 8B-aligned (w0 even, PW even, all strides even)
    auto loadr = [&](ull dst[8], const float* q) {
        #pragma unroll
        for (int r = 0; r < 4; r++) {
            dst[2 * r]     = *reinterpret_cast<const ull*>(q + r * PW);
            dst[2 * r + 1] = *reinterpret_cast<const ull*>(q + r * PW + 2);
        }
    };
    auto addr = [&](int it) {
        return base + (size_t)(it / 3) * CHS + (size_t)(it % 3) * PLANE;
    };
    auto compute = [&](const ull buf[8], const ull* wt) {
        ull vp[4][4];
        #pragma unroll
        for (int r = 0; r < 4; r++) {
            vp[r][0] = dup_lo(buf[2 * r]);
            vp[r][1] = dup_hi(buf[2 * r]);
            vp[r][2] = dup_lo(buf[2 * r + 1]);
            vp[r][3] = dup_hi(buf[2 * r + 1]);
        }
        #pragma unroll
        for (int kh = 0; kh < 3; kh++) {
            #pragma unroll
            for (int kw = 0; kw < 3; kw++) {
                const ull* wkk = wt + (kh * 3 + kw) * COP;
                #pragma unroll
                for (int cp = 0; cp < COP; cp += 2) {
                    ulonglong2 wv = *reinterpret_cast<const ulonglong2*>(wkk + cp);
                    ffma2(acc[0][cp], vp[kh][kw],         wv.x);
                    ffma2(acc[1][cp], vp[kh][kw + 1],     wv.x);
                    ffma2(acc[2][cp], vp[kh + 1][kw],     wv.x);
                    ffma2(acc[3][cp], vp[kh + 1][kw + 1], wv.x);
                    ffma2(acc[0][cp + 1], vp[kh][kw],         wv.y);
                    ffma2(acc[1][cp + 1], vp[kh][kw + 1],     wv.y);
                    ffma2(acc[2][cp + 1], vp[kh + 1][kw],     wv.y);
                    ffma2(acc[3][cp + 1], vp[kh + 1][kw + 1], wv.y);
                }
            }
        }
    };

    ull bufA[8], bufB[8];
    loadr(bufA, addr(0));
    if constexpr (CIN == 1) {
        loadr(bufB, addr(1));
        compute(bufA, wsp);
        loadr(bufA, addr(2));
        compute(bufB, wsp + 9 * COP);
        compute(bufA, wsp + 18 * COP);
    } else {
        constexpr int NIT = 3 * CIN;
        #pragma unroll 1
        for (int it = 0; it < NIT; it += 2) {
            loadr(bufB, addr(it + 1));
            compute(bufA, wsp + it * 9 * COP);
            if (it + 2 < NIT) loadr(bufA, addr(it + 2));
            compute(bufB, wsp + (it + 1) * 9 * COP);
        }
    }

    size_t obase = ((size_t)(b * COUT) * PD + (d + 1)) * PLANE
                 + (size_t)(h0 + 1) * PW + (w0 + 1);
    #pragma unroll
    for (int cp = 0; cp < COP; cp++) {
        size_t o0 = obase + (size_t)(co_base + 2 * cp) * CHS;
        #pragma unroll
        for (int pp = 0; pp < 4; pp++) {
            float x, y;
            unpack2(acc[pp][cp], x, y);
            if (RELU) { x = fmaxf(x, 0.f); y = fmaxf(y, 0.f); }
            size_t o = o0 + (size_t)(pp >> 1) * PW + (pp & 1);
            out[o] = x;
            out[o + CHS] = y;
        }
    }
}

// ---------------------------------------------------------------------------
// Final conv: CIN -> 1 channel, padded input, UNPADDED output, no ReLU.
// 2x2 patch, double-buffered prefetch (R4 version).
// ---------------------------------------------------------------------------
template<int CIN, int D, int H, int W>
__global__ void __launch_bounds__(128) conv3d_s(
    const float* __restrict__ in, const float* __restrict__ wgt,
    float* __restrict__ out)
{
    constexpr int PW = W + 2, PH = H + 2, PD = D + 2;
    constexpr int PLANE = PH * PW;
    constexpr int CHS = PD * PLANE;
    constexpr int HP = H / 2, WP = W / 2;

    __shared__ float ws[CIN * 27];
    for (int i = threadIdx.x; i < CIN * 27; i += 128)
        ws[i] = wgt[i];
    __syncthreads();

    int sidx = blockIdx.x * 128 + threadIdx.x;
    int wp = sidx % WP;
    int t  = sidx / WP;
    int hp = t % HP;
    t /= HP;
    int d = t % D;
    int b = t / D;
    int h0 = hp * 2, w0 = wp * 2;

    float sacc[4] = {0.f, 0.f, 0.f, 0.f};
    const float* base = in + (size_t)b * CIN * CHS
                           + (size_t)d * PLANE + (size_t)h0 * PW + w0;

    auto loadr = [&](ull dst[8], const float* q) {
        #pragma unroll
        for (int r = 0; r < 4; r++) {
            dst[2 * r]     = *reinterpret_cast<const ull*>(q + r * PW);
            dst[2 * r + 1] = *reinterpret_cast<const ull*>(q + r * PW + 2);
        }
    };
    auto addr = [&](int it) {
        return base + (size_t)(it / 3) * CHS + (size_t)(it % 3) * PLANE;
    };
    auto compute = [&](const ull buf[8], const float* wt) {
        float v[4][4];
        #pragma unroll
        for (int r = 0; r < 4; r++) {
            unpack2(buf[2 * r],     v[r][0], v[r][1]);
            unpack2(buf[2 * r + 1], v[r][2], v[r][3]);
        }
        #pragma unroll
        for (int kh = 0; kh < 3; kh++) {
            #pragma unroll
            for (int kw = 0; kw < 3; kw++) {
                float wv = wt[kh * 3 + kw];
                sacc[0] = fmaf(v[kh][kw],         wv, sacc[0]);
                sacc[1] = fmaf(v[kh][kw + 1],     wv, sacc[1]);
                sacc[2] = fmaf(v[kh + 1][kw],     wv, sacc[2]);
                sacc[3] = fmaf(v[kh + 1][kw + 1], wv, sacc[3]);
            }
        }
    };

    ull bufA[8], bufB[8];
    loadr(bufA, addr(0));
    constexpr int NIT = 3 * CIN;
    #pragma unroll 1
    for (int it = 0; it < NIT; it += 2) {
        loadr(bufB, addr(it + 1));
        compute(bufA, ws + it * 9);
        if (it + 2 < NIT) loadr(bufA, addr(it + 2));
        compute(bufB, ws + (it + 1) * 9);
    }

    size_t bo = ((size_t)b * D + d) * (H * W) + (size_t)h0 * W + w0;
    out[bo]         = sacc[0];
    out[bo + 1]     = sacc[1];
    out[bo + W]     = sacc[2];
    out[bo + W + 1] = sacc[3];
}

// ---------------------------------------------------------------------------
// Scale-0 L1 cost volume -> PADDED cost buffer [B,1,14,34,82]
// ---------------------------------------------------------------------------
__global__ void cost0_k(const float* __restrict__ fl, const float* __restrict__ fr,
                        float* __restrict__ cost)
{
    int idx = blockIdx.x * 256 + threadIdx.x;   // 8*12*32*80
    int w  = idx % 80;
    int h  = (idx / 80) % 32;
    int dd = (idx / (80 * 32)) % 12;
    int b  = idx / (80 * 32 * 12);
    int src = w - dd;
    const float* flb = fl + (size_t)b * 8 * 32 * 80 + h * 80;
    const float* frb = fr + (size_t)b * 8 * 32 * 80 + h * 80;
    float s = 0.f;
    #pragma unroll
    for (int c = 0; c < 8; c++) {
        float a = flb[c * 32 * 80 + w];
        float r = (src >= 0) ? frb[c * 32 * 80 + src] : 0.f;
        s += fabsf(a - r);
    }
    cost[((size_t)b * 14 + dd + 1) * (34 * 82) + (h + 1) * 82 + (w + 1)] = s;
}

// ---------------------------------------------------------------------------
// Residual cost volume with FUSED vertical downsample (former down_v):
// each thread first computes its own wflow value from dtmp (the horizontally
// downsampled full-height pred), then computes all 5 shifts of the L1 warp
// cost. Writes PADDED cost buffer [B,1,7,H+2,W+2].
// ---------------------------------------------------------------------------
template<int R, int H, int W>
__global__ void costres_k(const float* __restrict__ fl, const float* __restrict__ fr,
                          const float* __restrict__ dtmp, float* __restrict__ cost,
                          float mul)
{
    constexpr int PW = W + 2, PH = H + 2;
    int idx = blockIdx.x * 256 + threadIdx.x;   // 8*H*W
    int w = idx % W;
    int h = (idx / W) % H;
    int b = idx / (W * H);

    // ---- inline vertical triangle downsample (identical math to down_v) ----
    float fy = ((float)h + 0.5f) * (float)R - 0.5f;
    const float invR = 1.0f / (float)R;
    int ylo = max(0, (int)ceilf(fy - (float)R));
    int yhi = min(FH - 1, (int)floorf(fy + (float)R));
    const float* col = dtmp + (size_t)b * FH * W + w;
    float dacc = 0.f, wys = 0.f;
    for (int y = ylo; y <= yhi; y++) {
        float wy = fmaxf(0.f, 1.f - fabsf((float)y - fy) * invR);
        wys += wy;
        dacc += wy * col[(size_t)y * W];
    }
    float disp = dacc / wys * mul;

    // ---- residual cost over 5 shifts (shared fractional weight) ----
    // s = 0: xs = w - (disp - (-2)) = w - disp - 2; xs(s) = xs0 + s
    float xs0 = (float)w - disp - 2.0f;
    float x0f = floorf(xs0);
    float w1 = xs0 - x0f;          // shared across all 5 shifts
    int x0 = (int)x0f;

    bool inb[6];
    int ix[6];
    #pragma unroll
    for (int j = 0; j < 6; j++) {
        int xi = x0 + j;
        inb[j] = (xi >= 0) && (xi <= W - 1);
        ix[j]  = min(max(xi, 0), W - 1);
    }

    const float* flb = fl + ((size_t)b * 8 * H + h) * W;
    const float* frb = fr + ((size_t)b * 8 * H + h) * W;

    float costs[5] = {0.f, 0.f, 0.f, 0.f, 0.f};
    #pragma unroll
    for (int c = 0; c < 8; c++) {
        float a = flb[c * H * W + w];
        const float* frc = frb + c * H * W;
        float v[6];
        #pragma unroll
        for (int j = 0; j < 6; j++)
            v[j] = inb[j] ? frc[ix[j]] : 0.f;
        #pragma unroll
        for (int s = 0; s < 5; s++)
            costs[s] += fabsf(a - (v[s] * (1.f - w1) + v[s + 1] * w1));
    }

    size_t obase = ((size_t)b * 7 + 1) * (PH * PW) + (h + 1) * PW + (w + 1);
    #pragma unroll
    for (int s = 0; s < 5; s++)
        cost[obase + (size_t)s * (PH * PW)] = costs[s];
}

// ---------------------------------------------------------------------------
// Softargmin disparity regression (reads UNPADDED cost). Fast exp/div —
// softmax relative error ~1e-6, far inside the 1e-3 budget.
// ---------------------------------------------------------------------------
template<int DT, int START, int H, int W>
__global__ void dispreg_k(const float* __restrict__ cost, float* __restrict__ dout,
                          float scale)
{
    int idx = blockIdx.x * 256 + threadIdx.x;   // 8*H*W
    int w = idx % W;
    int h = (idx / W) % H;
    int b = idx / (W * H);
    float c[DT];
    #pragma unroll
    for (int i = 0; i < DT; i++)
        c[i] = cost[(((size_t)b * DT + i) * H + h) * W + w];
    float mn = c[0];
    #pragma unroll
    for (int i = 1; i < DT; i++) mn = fminf(mn, c[i]);
    float s = 0.f, num = 0.f;
    #pragma unroll
    for (int i = 0; i < DT; i++) {
        float p = __expf(mn - c[i]);
        s += p;
        num += p * (float)(START + i);
    }
    dout[idx] = __fdividef(num, s) * scale;
}

// ---------------------------------------------------------------------------
// Bilinear upsample to 512x1280 (jax half-pixel), 4 px/thread (float4 I/O),
// optional add of previous full-res pred, optional depth output.
// ---------------------------------------------------------------------------
template<int IH, int IW, bool ADD, bool DEPTH>
__global__ void up_k(const float* __restrict__ src, const float* __restrict__ addsrc,
                     float* __restrict__ outp, float* __restrict__ depthp)
{
    int idx = blockIdx.x * 256 + threadIdx.x;   // 8*512*320
    int oq = idx % (FW / 4);
    int oy = (idx / (FW / 4)) % FH;
    int b  = idx / ((FW / 4) * FH);

    float fy = ((float)oy + 0.5f) * ((float)IH / (float)FH) - 0.5f;
    fy = fminf(fmaxf(fy, 0.f), (float)(IH - 1));
    int y0 = (int)fy; float gy = fy - (float)y0; int y1 = min(y0 + 1, IH - 1);
    const float* sb = src + (size_t)b * IH * IW;
    const float* r0 = sb + y0 * IW;
    const float* r1 = sb + y1 * IW;

    size_t base = ((size_t)b * FH + oy) * FW + oq * 4;
    float4 res, dep;
    float* rp = reinterpret_cast<float*>(&res);
    float* dp = reinterpret_cast<float*>(&dep);
    #pragma unroll
    for (int j = 0; j < 4; j++) {
        int ox = oq * 4 + j;
        float fx = ((float)ox + 0.5f) * ((float)IW / (float)FW) - 0.5f;
        fx = fminf(fmaxf(fx, 0.f), (float)(IW - 1));
        int x0 = (int)fx; float gx = fx - (float)x0; int x1 = min(x0 + 1, IW - 1);
        float v = (r0[x0] * (1.f - gx) + r0[x1] * gx) * (1.f - gy)
                + (r1[x0] * (1.f - gx) + r1[x1] * gx) * gy;
        rp[j] = v;
    }
    if (ADD) {
        float4 a = *reinterpret_cast<const float4*>(addsrc + base);
        res.x += a.x; res.y += a.y; res.z += a.z; res.w += a.w;
    }
    *reinterpret_cast<float4*>(outp + base) = res;
    if (DEPTH) {
        #pragma unroll
        for (int j = 0; j < 4; j++)
            dp[j] = fminf(fmaxf(64.0f / fabsf(rp[j]), 0.1f), 100.0f);
        *reinterpret_cast<float4*>(depthp + base) = dep;
    }
}

// ---------------------------------------------------------------------------
// Separable antialiased downsample (jax triangle kernel, width R, per-axis
// normalized). Horizontal pass only: 1280 -> OW at full height 512.
// (Vertical pass is fused into costres_k.)
// ---------------------------------------------------------------------------
template<int R, int OW>
__global__ void down_h(const float* __restrict__ src, float* __restrict__ tmp)
{
    int idx = blockIdx.x * 256 + threadIdx.x;   // 8*512*OW
    int ox = idx % OW;
    int y  = (idx / OW) % FH;
    int b  = idx / (OW * FH);
    float fx = ((float)ox + 0.5f) * (float)R - 0.5f;
    const float invR = 1.0f / (float)R;
    int xlo = max(0, (int)ceilf(fx - (float)R));
    int xhi = min(FW - 1, (int)floorf(fx + (float)R));
    const float* row = src + ((size_t)b * FH + y) * FW;
    float acc = 0.f, wxs = 0.f;
    for (int x = xlo; x <= xhi; x++) {
        float wx = fmaxf(0.f, 1.f - fabsf((float)x - fx) * invR);
        wxs += wx;
        acc += wx * row[x];
    }
    tmp[idx] = acc / wxs;
}

// ---------------------------------------------------------------------------
// Launch
// ---------------------------------------------------------------------------
extern "C" void kernel_launch(void* const* d_in, const int* in_sizes, int n_in,
                              void* d_out, int out_size)
{
    (void)in_sizes; (void)n_in; (void)out_size;
    float* scr = nullptr;
    cudaGetSymbolAddress((void**)&scr, g_scratch);

    const float* fl0 = (const float*)d_in[0];
    const float* fr0 = (const float*)d_in[1];
    const float* fl1 = (const float*)d_in[2];
    const float* fr1 = (const float*)d_in[3];
    const float* fl2 = (const float*)d_in[4];
    const float* fr2 = (const float*)d_in[5];
    const float* w_in0  = (const float*)d_in[6];
    const float* w_mid0 = (const float*)d_in[7];
    const float* w_out0 = (const float*)d_in[8];
    const float* w_in1  = (const float*)d_in[9];
    const float* w_mid1 = (const float*)d_in[10];
    const float* w_out1 = (const float*)d_in[11];
    const float* w_in2  = (const float*)d_in[12];
    const float* w_mid2 = (const float*)d_in[13];
    const float* w_out2 = (const float*)d_in[14];

    // padded arena layout (floats)
    float* act0a  = scr + 0;          // 8*16*14*34*82 = 4,996,096
    float* act0b  = scr + 4996096;
    float* cost0p = scr + 9992192;    // 8*14*34*82    =   312,256
    float* cost0u = scr + 10304448;   // 8*12*32*80    =   245,760
    float* act1a  = scr + 10550208;   // 8*4*7*66*162  = 2,395,008
    float* act1b  = scr + 12945216;
    float* cost1p = scr + 15340224;   // 8*7*66*162    =   598,752
    float* cost1u = scr + 15938976;   // 8*5*64*160    =   409,600
    float* act2a  = scr + 16348576;   // 8*4*7*130*322 = 9,376,640
    float* act2b  = scr + 25725216;
    float* cost2p = scr + 35101856;   // 8*7*130*322   = 2,344,160
    float* cost2u = scr + 37446016;   // 8*5*128*320   = 1,638,400
    float* dd0    = scr + 39084416;   //   20,480
    float* dd1    = scr + 39104896;   //   81,920
    float* dd2    = scr + 39186816;   //  327,680
    float* dtmp   = scr + 39514496;   // 8*512*320 = 1,310,720 (max of passes)

    float* out = (float*)d_out;
    const size_t NPX = (size_t)8 * 512 * 1280;
    float* pred0 = out;
    float* pred1 = out + NPX;
    float* pred2 = out + 2 * NPX;
    float* depth = out + 3 * NPX;

    // ---- scale 0 : D=12, H=32, W=80, 16 channels ----
    cost0_k<<<960, 256>>>(fl0, fr0, cost0p);
    conv3d_p<1, 16, 2, 12, 32, 80, true ><<<1920, 128>>>(cost0p, w_in0, act0a);
    conv3d_p<16, 16, 2, 12, 32, 80, true ><<<1920, 128>>>(act0a, w_mid0 + 0 * 6912, act0b);
    conv3d_p<16, 16, 2, 12, 32, 80, true ><<<1920, 128>>>(act0b, w_mid0 + 1 * 6912, act0a);
    conv3d_p<16, 16, 2, 12, 32, 80, true ><<<1920, 128>>>(act0a, w_mid0 + 2 * 6912, act0b);
    conv3d_p<16, 16, 2, 12, 32, 80, true ><<<1920, 128>>>(act0b, w_mid0 + 3 * 6912, act0a);
    conv3d_s<16, 12, 32, 80><<<480, 128>>>(act0a, w_out0, cost0u);
    dispreg_k<12, 0, 32, 80><<<80, 256>>>(cost0u, dd0, 16.0f);
    up_k<32, 80, false, true><<<5120, 256>>>(dd0, nullptr, pred0, depth);

    // ---- scale 1 : D=5, H=64, W=160, 4 channels ----
    down_h<8, 160><<<2560, 256>>>(pred0, dtmp);
    costres_k<8, 64, 160><<<320, 256>>>(fl1, fr1, dtmp, cost1p, 0.125f);
    conv3d_p<1, 4, 2, 5, 64, 160, true ><<<800, 128>>>(cost1p, w_in1, act1a);
    conv3d_p<4, 4, 2, 5, 64, 160, true ><<<800, 128>>>(act1a, w_mid1 + 0 * 432, act1b);
    conv3d_p<4, 4, 2, 5, 64, 160, true ><<<800, 128>>>(act1b, w_mid1 + 1 * 432, act1a);
    conv3d_p<4, 4, 2, 5, 64, 160, true ><<<800, 128>>>(act1a, w_mid1 + 2 * 432, act1b);
    conv3d_p<4, 4, 2, 5, 64, 160, true ><<<800, 128>>>(act1b, w_mid1 + 3 * 432, act1a);
    conv3d_s<4, 5, 64, 160><<<800, 128>>>(act1a, w_out1, cost1u);
    dispreg_k<5, -2, 64, 160><<<320, 256>>>(cost1u, dd1, 8.0f);
    up_k<64, 160, true, false><<<5120, 256>>>(dd1, pred0, pred1, nullptr);

    // ---- scale 2 : D=5, H=128, W=320, 4 channels ----
    down_h<4, 320><<<5120, 256>>>(pred1, dtmp);
    costres_k<4, 128, 320><<<1280, 256>>>(fl2, fr2, dtmp, cost2p, 0.25f);
    conv3d_p<1, 4, 2, 5, 128, 320, true ><<<3200, 128>>>(cost2p, w_in2, act2a);
    conv3d_p<4, 4, 2, 5, 128, 320, true ><<<3200, 128>>>(act2a, w_mid2 + 0 * 432, act2b);
    conv3d_p<4, 4, 2, 5, 128, 320, true ><<<3200, 128>>>(act2b, w_mid2 + 1 * 432, act2a);
    conv3d_p<4, 4, 2, 5, 128, 320, true ><<<3200, 128>>>(act2a, w_mid2 + 2 * 432, act2b);
    conv3d_p<4, 4, 2, 5, 128, 320, true ><<<3200, 128>>>(act2b, w_mid2 + 3 * 432, act2a);
    conv3d_s<4, 5, 128, 320><<<3200, 128>>>(act2a, w_out2, cost2u);
    dispreg_k<5, -2, 128, 320><<<1280, 256>>>(cost2u, dd2, 4.0f);
    up_k<128, 320, true, false><<<5120, 256>>>(dd2, pred1, pred2, nullptr);
}

// round 12
// speedup vs baseline: 1.1287x; 1.0114x over previous
#include <cuda_runtime.h>
#include <cstdint>
#include <cstddef>
#include <math.h>

using ull = unsigned long long;
#define DEV_INLINE __device__ __forceinline__

DEV_INLINE void ffma2(ull &acc, ull a, ull w) {
    asm("fma.rn.f32x2 %0, %1, %2, %0;" : "+l"(acc) : "l"(a), "l"(w));
}
DEV_INLINE ull pack2(float lo, float hi) {
    ull r; asm("mov.b64 %0, {%1, %2};" : "=l"(r) : "f"(lo), "f"(hi)); return r;
}
DEV_INLINE void unpack2(ull v, float &lo, float &hi) {
    asm("mov.b64 {%0, %1}, %2;" : "=f"(lo), "=f"(hi) : "l"(v));
}
DEV_INLINE ull dup_lo(ull v) { float a, b; unpack2(v, a, b); return pack2(a, a); }
DEV_INLINE ull dup_hi(ull v) { float a, b; unpack2(v, a, b); return pack2(b, b); }

constexpr int FH = 512, FW = 1280;

// ---------------------------------------------------------------------------
// Scratch arena. Zero-initialized at module load; conv halos are NEVER written
// by any kernel, so they remain zero across all calls (deterministic).
// ---------------------------------------------------------------------------
__device__ float g_scratch[41000000];

// ---------------------------------------------------------------------------
// 3x3x3 SAME conv3d on ZERO-PADDED input [B,CIN,D+2,H+2,W+2], writes padded
// interior of out. ReLU optional. cout-pairs in f32x2 lanes, LDG.64 input
// loads, LDS.128 weights, double-buffered prefetch (R4 configuration — the
// measured local optimum: COP=2, no reg cap, distance-1 prefetch).
// ---------------------------------------------------------------------------
template<int CIN, int COUT, int COP, int D, int H, int W, bool RELU>
__global__ void __launch_bounds__(128) conv3d_p(
    const float* __restrict__ in, const float* __restrict__ wgt,
    float* __restrict__ out)
{
    constexpr int PW = W + 2, PH = H + 2, PD = D + 2;
    constexpr int PLANE = PH * PW;
    constexpr int CHS = PD * PLANE;
    constexpr int HP = H / 2, WP = W / 2;
    constexpr int SPB = 8 * D * HP * WP / 128;
    constexpr int NW = CIN * 27 * COP;

    __shared__ alignas(16) float2 ws[NW];
    const int g = blockIdx.x / SPB;
    const int co_base = g * 2 * COP;
    for (int i = threadIdx.x; i < NW; i += 128) {
        int cp  = i % COP;
        int pos = (i / COP) % 27;
        int ci  = i / (COP * 27);
        float2 wv;
        wv.x = wgt[((co_base + 2 * cp)     * CIN + ci) * 27 + pos];
        wv.y = wgt[((co_base + 2 * cp + 1) * CIN + ci) * 27 + pos];
        ws[(ci * 27 + pos) * COP + cp] = wv;
    }
    __syncthreads();

    int sidx = (blockIdx.x % SPB) * 128 + threadIdx.x;
    int wp = sidx % WP;
    int t  = sidx / WP;
    int hp = t % HP;
    t /= HP;
    int d = t % D;
    int b = t / D;
    int h0 = hp * 2, w0 = wp * 2;

    ull acc[4][COP];
    #pragma unroll
    for (int p = 0; p < 4; p++)
        #pragma unroll
        for (int c = 0; c < COP; c++) acc[p][c] = 0ULL;

    const float* base = in + (size_t)b * CIN * CHS
                           + (size_t)d * PLANE + (size_t)h0 * PW + w0;
    const ull* wsp = reinterpret_cast<const ull*>(ws);

    // patch rows are 8B-aligned (w0 even, PW even, all strides even)
    auto loadr = [&](ull dst[8], const float* q) {
        #pragma unroll
        for (int r = 0; r < 4; r++) {
            dst[2 * r]     = *reinterpret_cast<const ull*>(q + r * PW);
            dst[2 * r + 1] = *reinterpret_cast<const ull*>(q + r * PW + 2);
        }
    };
    auto addr = [&](int it) {
        return base + (size_t)(it / 3) * CHS + (size_t)(it % 3) * PLANE;
    };
    auto compute = [&](const ull buf[8], const ull* wt) {
        ull vp[4][4];
        #pragma unroll
        for (int r = 0; r < 4; r++) {
            vp[r][0] = dup_lo(buf[2 * r]);
            vp[r][1] = dup_hi(buf[2 * r]);
            vp[r][2] = dup_lo(buf[2 * r + 1]);
            vp[r][3] = dup_hi(buf[2 * r + 1]);
        }
        #pragma unroll
        for (int kh = 0; kh < 3; kh++) {
            #pragma unroll
            for (int kw = 0; kw < 3; kw++) {
                const ull* wkk = wt + (kh * 3 + kw) * COP;
                #pragma unroll
                for (int cp = 0; cp < COP; cp += 2) {
                    ulonglong2 wv = *reinterpret_cast<const ulonglong2*>(wkk + cp);
                    ffma2(acc[0][cp], vp[kh][kw],         wv.x);
                    ffma2(acc[1][cp], vp[kh][kw + 1],     wv.x);
                    ffma2(acc[2][cp], vp[kh + 1][kw],     wv.x);
                    ffma2(acc[3][cp], vp[kh + 1][kw + 1], wv.x);
                    ffma2(acc[0][cp + 1], vp[kh][kw],         wv.y);
                    ffma2(acc[1][cp + 1], vp[kh][kw + 1],     wv.y);
                    ffma2(acc[2][cp + 1], vp[kh + 1][kw],     wv.y);
                    ffma2(acc[3][cp + 1], vp[kh + 1][kw + 1], wv.y);
                }
            }
        }
    };

    ull bufA[8], bufB[8];
    loadr(bufA, addr(0));
    if constexpr (CIN == 1) {
        loadr(bufB, addr(1));
        compute(bufA, wsp);
        loadr(bufA, addr(2));
        compute(bufB, wsp + 9 * COP);
        compute(bufA, wsp + 18 * COP);
    } else {
        constexpr int NIT = 3 * CIN;
        #pragma unroll 1
        for (int it = 0; it < NIT; it += 2) {
            loadr(bufB, addr(it + 1));
            compute(bufA, wsp + it * 9 * COP);
            if (it + 2 < NIT) loadr(bufA, addr(it + 2));
            compute(bufB, wsp + (it + 1) * 9 * COP);
        }
    }

    size_t obase = ((size_t)(b * COUT) * PD + (d + 1)) * PLANE
                 + (size_t)(h0 + 1) * PW + (w0 + 1);
    #pragma unroll
    for (int cp = 0; cp < COP; cp++) {
        size_t o0 = obase + (size_t)(co_base + 2 * cp) * CHS;
        #pragma unroll
        for (int pp = 0; pp < 4; pp++) {
            float x, y;
            unpack2(acc[pp][cp], x, y);
            if (RELU) { x = fmaxf(x, 0.f); y = fmaxf(y, 0.f); }
            size_t o = o0 + (size_t)(pp >> 1) * PW + (pp & 1);
            out[o] = x;
            out[o + CHS] = y;
        }
    }
}

// ---------------------------------------------------------------------------
// Final conv: CIN -> 1 channel, padded input, UNPADDED output, no ReLU.
// 2x2 patch, double-buffered prefetch (R4 version).
// ---------------------------------------------------------------------------
template<int CIN, int D, int H, int W>
__global__ void __launch_bounds__(128) conv3d_s(
    const float* __restrict__ in, const float* __restrict__ wgt,
    float* __restrict__ out)
{
    constexpr int PW = W + 2, PH = H + 2, PD = D + 2;
    constexpr int PLANE = PH * PW;
    constexpr int CHS = PD * PLANE;
    constexpr int HP = H / 2, WP = W / 2;

    __shared__ float ws[CIN * 27];
    for (int i = threadIdx.x; i < CIN * 27; i += 128)
        ws[i] = wgt[i];
    __syncthreads();

    int sidx = blockIdx.x * 128 + threadIdx.x;
    int wp = sidx % WP;
    int t  = sidx / WP;
    int hp = t % HP;
    t /= HP;
    int d = t % D;
    int b = t / D;
    int h0 = hp * 2, w0 = wp * 2;

    float sacc[4] = {0.f, 0.f, 0.f, 0.f};
    const float* base = in + (size_t)b * CIN * CHS
                           + (size_t)d * PLANE + (size_t)h0 * PW + w0;

    auto loadr = [&](ull dst[8], const float* q) {
        #pragma unroll
        for (int r = 0; r < 4; r++) {
            dst[2 * r]     = *reinterpret_cast<const ull*>(q + r * PW);
            dst[2 * r + 1] = *reinterpret_cast<const ull*>(q + r * PW + 2);
        }
    };
    auto addr = [&](int it) {
        return base + (size_t)(it / 3) * CHS + (size_t)(it % 3) * PLANE;
    };
    auto compute = [&](const ull buf[8], const float* wt) {
        float v[4][4];
        #pragma unroll
        for (int r = 0; r < 4; r++) {
            unpack2(buf[2 * r],     v[r][0], v[r][1]);
            unpack2(buf[2 * r + 1], v[r][2], v[r][3]);
        }
        #pragma unroll
        for (int kh = 0; kh < 3; kh++) {
            #pragma unroll
            for (int kw = 0; kw < 3; kw++) {
                float wv = wt[kh * 3 + kw];
                sacc[0] = fmaf(v[kh][kw],         wv, sacc[0]);
                sacc[1] = fmaf(v[kh][kw + 1],     wv, sacc[1]);
                sacc[2] = fmaf(v[kh + 1][kw],     wv, sacc[2]);
                sacc[3] = fmaf(v[kh + 1][kw + 1], wv, sacc[3]);
            }
        }
    };

    ull bufA[8], bufB[8];
    loadr(bufA, addr(0));
    constexpr int NIT = 3 * CIN;
    #pragma unroll 1
    for (int it = 0; it < NIT; it += 2) {
        loadr(bufB, addr(it + 1));
        compute(bufA, ws + it * 9);
        if (it + 2 < NIT) loadr(bufA, addr(it + 2));
        compute(bufB, ws + (it + 1) * 9);
    }

    size_t bo = ((size_t)b * D + d) * (H * W) + (size_t)h0 * W + w0;
    out[bo]         = sacc[0];
    out[bo + 1]     = sacc[1];
    out[bo + W]     = sacc[2];
    out[bo + W + 1] = sacc[3];
}

// ---------------------------------------------------------------------------
// Scale-0 L1 cost volume -> PADDED cost buffer [B,1,14,34,82]
// ---------------------------------------------------------------------------
__global__ void cost0_k(const float* __restrict__ fl, const float* __restrict__ fr,
                        float* __restrict__ cost)
{
    int idx = blockIdx.x * 256 + threadIdx.x;   // 8*12*32*80
    int w  = idx % 80;
    int h  = (idx / 80) % 32;
    int dd = (idx / (80 * 32)) % 12;
    int b  = idx / (80 * 32 * 12);
    int src = w - dd;
    const float* flb = fl + (size_t)b * 8 * 32 * 80 + h * 80;
    const float* frb = fr + (size_t)b * 8 * 32 * 80 + h * 80;
    float s = 0.f;
    #pragma unroll
    for (int c = 0; c < 8; c++) {
        float a = flb[c * 32 * 80 + w];
        float r = (src >= 0) ? frb[c * 32 * 80 + src] : 0.f;
        s += fabsf(a - r);
    }
    cost[((size_t)b * 14 + dd + 1) * (34 * 82) + (h + 1) * 82 + (w + 1)] = s;
}

// ---------------------------------------------------------------------------
// Residual cost volume with FUSED vertical downsample (former down_v):
// each thread first computes its own wflow value from dtmp (the horizontally
// downsampled full-height pred), then computes all 5 shifts of the L1 warp
// cost. Writes PADDED cost buffer [B,1,7,H+2,W+2].
// ---------------------------------------------------------------------------
template<int R, int H, int W>
__global__ void costres_k(const float* __restrict__ fl, const float* __restrict__ fr,
                          const float* __restrict__ dtmp, float* __restrict__ cost,
                          float mul)
{
    constexpr int PW = W + 2, PH = H + 2;
    int idx = blockIdx.x * 256 + threadIdx.x;   // 8*H*W
    int w = idx % W;
    int h = (idx / W) % H;
    int b = idx / (W * H);

    // ---- inline vertical triangle downsample (identical math to down_v) ----
    float fy = ((float)h + 0.5f) * (float)R - 0.5f;
    const float invR = 1.0f / (float)R;
    int ylo = max(0, (int)ceilf(fy - (float)R));
    int yhi = min(FH - 1, (int)floorf(fy + (float)R));
    const float* col = dtmp + (size_t)b * FH * W + w;
    float dacc = 0.f, wys = 0.f;
    for (int y = ylo; y <= yhi; y++) {
        float wy = fmaxf(0.f, 1.f - fabsf((float)y - fy) * invR);
        wys += wy;
        dacc += wy * col[(size_t)y * W];
    }
    float disp = dacc / wys * mul;

    // ---- residual cost over 5 shifts (shared fractional weight) ----
    // s = 0: xs = w - (disp - (-2)) = w - disp - 2; xs(s) = xs0 + s
    float xs0 = (float)w - disp - 2.0f;
    float x0f = floorf(xs0);
    float w1 = xs0 - x0f;          // shared across all 5 shifts
    int x0 = (int)x0f;

    bool inb[6];
    int ix[6];
    #pragma unroll
    for (int j = 0; j < 6; j++) {
        int xi = x0 + j;
        inb[j] = (xi >= 0) && (xi <= W - 1);
        ix[j]  = min(max(xi, 0), W - 1);
    }

    const float* flb = fl + ((size_t)b * 8 * H + h) * W;
    const float* frb = fr + ((size_t)b * 8 * H + h) * W;

    float costs[5] = {0.f, 0.f, 0.f, 0.f, 0.f};
    #pragma unroll
    for (int c = 0; c < 8; c++) {
        float a = flb[c * H * W + w];
        const float* frc = frb + c * H * W;
        float v[6];
        #pragma unroll
        for (int j = 0; j < 6; j++)
            v[j] = inb[j] ? frc[ix[j]] : 0.f;
        #pragma unroll
        for (int s = 0; s < 5; s++)
            costs[s] += fabsf(a - (v[s] * (1.f - w1) + v[s + 1] * w1));
    }

    size_t obase = ((size_t)b * 7 + 1) * (PH * PW) + (h + 1) * PW + (w + 1);
    #pragma unroll
    for (int s = 0; s < 5; s++)
        cost[obase + (size_t)s * (PH * PW)] = costs[s];
}

// ---------------------------------------------------------------------------
// Softargmin disparity regression (reads UNPADDED cost). Fast exp/div —
// softmax relative error ~1e-6, far inside the 1e-3 budget.
// ---------------------------------------------------------------------------
template<int DT, int START, int H, int W>
__global__ void dispreg_k(const float* __restrict__ cost, float* __restrict__ dout,
                          float scale)
{
    int idx = blockIdx.x * 256 + threadIdx.x;   // 8*H*W
    int w = idx % W;
    int h = (idx / W) % H;
    int b = idx / (W * H);
    float c[DT];
    #pragma unroll
    for (int i = 0; i < DT; i++)
        c[i] = cost[(((size_t)b * DT + i) * H + h) * W + w];
    float mn = c[0];
    #pragma unroll
    for (int i = 1; i < DT; i++) mn = fminf(mn, c[i]);
    float s = 0.f, num = 0.f;
    #pragma unroll
    for (int i = 0; i < DT; i++) {
        float p = __expf(mn - c[i]);
        s += p;
        num += p * (float)(START + i);
    }
    dout[idx] = __fdividef(num, s) * scale;
}

// ---------------------------------------------------------------------------
// FUSED upsample + horizontal triangle downsample.
// One block = one full-res row (b, oy): 320 threads x 4 px compute the
// bilinear upsample (+optional add of prev pred, +optional depth), write the
// full-res row, stage it in smem, then compute the horizontal triangle
// downsample of that row into dtmp (identical math to the old down_h).
// ---------------------------------------------------------------------------
template<int IH, int IW, int R, int OW, bool ADD, bool DEPTH>
__global__ void __launch_bounds__(320) updown_k(
    const float* __restrict__ src, const float* __restrict__ addsrc,
    float* __restrict__ outp, float* __restrict__ depthp,
    float* __restrict__ dtmp)
{
    __shared__ float rowbuf[FW];
    int oy = blockIdx.x % FH;
    int b  = blockIdx.x / FH;
    int oq = threadIdx.x;             // 0..319, 4 px each

    float fy = ((float)oy + 0.5f) * ((float)IH / (float)FH) - 0.5f;
    fy = fminf(fmaxf(fy, 0.f), (float)(IH - 1));
    int y0 = (int)fy; float gy = fy - (float)y0; int y1 = min(y0 + 1, IH - 1);
    const float* sb = src + (size_t)b * IH * IW;
    const float* r0 = sb + y0 * IW;
    const float* r1 = sb + y1 * IW;

    size_t base = ((size_t)b * FH + oy) * FW + oq * 4;
    float4 res, dep;
    float* rp = reinterpret_cast<float*>(&res);
    float* dp = reinterpret_cast<float*>(&dep);
    #pragma unroll
    for (int j = 0; j < 4; j++) {
        int ox = oq * 4 + j;
        float fx = ((float)ox + 0.5f) * ((float)IW / (float)FW) - 0.5f;
        fx = fminf(fmaxf(fx, 0.f), (float)(IW - 1));
        int x0 = (int)fx; float gx = fx - (float)x0; int x1 = min(x0 + 1, IW - 1);
        float v = (r0[x0] * (1.f - gx) + r0[x1] * gx) * (1.f - gy)
                + (r1[x0] * (1.f - gx) + r1[x1] * gx) * gy;
        rp[j] = v;
    }
    if (ADD) {
        float4 a = *reinterpret_cast<const float4*>(addsrc + base);
        res.x += a.x; res.y += a.y; res.z += a.z; res.w += a.w;
    }
    *reinterpret_cast<float4*>(outp + base) = res;
    if (DEPTH) {
        #pragma unroll
        for (int j = 0; j < 4; j++)
            dp[j] = fminf(fmaxf(64.0f / fabsf(rp[j]), 0.1f), 100.0f);
        *reinterpret_cast<float4*>(depthp + base) = dep;
    }
    *reinterpret_cast<float4*>(rowbuf + oq * 4) = res;
    __syncthreads();

    // horizontal triangle downsample of this row (identical to old down_h)
    for (int ox = threadIdx.x; ox < OW; ox += 320) {
        float fx = ((float)ox + 0.5f) * (float)R - 0.5f;
        const float invR = 1.0f / (float)R;
        int xlo = max(0, (int)ceilf(fx - (float)R));
        int xhi = min(FW - 1, (int)floorf(fx + (float)R));
        float acc = 0.f, wxs = 0.f;
        for (int x = xlo; x <= xhi; x++) {
            float wx = fmaxf(0.f, 1.f - fabsf((float)x - fx) * invR);
            wxs += wx;
            acc += wx * rowbuf[x];
        }
        dtmp[((size_t)b * FH + oy) * OW + ox] = acc / wxs;
    }
}

// ---------------------------------------------------------------------------
// Plain bilinear upsample (final pred2; no downsample needed), 4 px/thread.
// ---------------------------------------------------------------------------
template<int IH, int IW, bool ADD, bool DEPTH>
__global__ void up_k(const float* __restrict__ src, const float* __restrict__ addsrc,
                     float* __restrict__ outp, float* __restrict__ depthp)
{
    int idx = blockIdx.x * 256 + threadIdx.x;   // 8*512*320
    int oq = idx % (FW / 4);
    int oy = (idx / (FW / 4)) % FH;
    int b  = idx / ((FW / 4) * FH);

    float fy = ((float)oy + 0.5f) * ((float)IH / (float)FH) - 0.5f;
    fy = fminf(fmaxf(fy, 0.f), (float)(IH - 1));
    int y0 = (int)fy; float gy = fy - (float)y0; int y1 = min(y0 + 1, IH - 1);
    const float* sb = src + (size_t)b * IH * IW;
    const float* r0 = sb + y0 * IW;
    const float* r1 = sb + y1 * IW;

    size_t base = ((size_t)b * FH + oy) * FW + oq * 4;
    float4 res, dep;
    float* rp = reinterpret_cast<float*>(&res);
    float* dp = reinterpret_cast<float*>(&dep);
    #pragma unroll
    for (int j = 0; j < 4; j++) {
        int ox = oq * 4 + j;
        float fx = ((float)ox + 0.5f) * ((float)IW / (float)FW) - 0.5f;
        fx = fminf(fmaxf(fx, 0.f), (float)(IW - 1));
        int x0 = (int)fx; float gx = fx - (float)x0; int x1 = min(x0 + 1, IW - 1);
        float v = (r0[x0] * (1.f - gx) + r0[x1] * gx) * (1.f - gy)
                + (r1[x0] * (1.f - gx) + r1[x1] * gx) * gy;
        rp[j] = v;
    }
    if (ADD) {
        float4 a = *reinterpret_cast<const float4*>(addsrc + base);
        res.x += a.x; res.y += a.y; res.z += a.z; res.w += a.w;
    }
    *reinterpret_cast<float4*>(outp + base) = res;
    if (DEPTH) {
        #pragma unroll
        for (int j = 0; j < 4; j++)
            dp[j] = fminf(fmaxf(64.0f / fabsf(rp[j]), 0.1f), 100.0f);
        *reinterpret_cast<float4*>(depthp + base) = dep;
    }
}

// ---------------------------------------------------------------------------
// Launch
// ---------------------------------------------------------------------------
extern "C" void kernel_launch(void* const* d_in, const int* in_sizes, int n_in,
                              void* d_out, int out_size)
{
    (void)in_sizes; (void)n_in; (void)out_size;
    float* scr = nullptr;
    cudaGetSymbolAddress((void**)&scr, g_scratch);

    const float* fl0 = (const float*)d_in[0];
    const float* fr0 = (const float*)d_in[1];
    const float* fl1 = (const float*)d_in[2];
    const float* fr1 = (const float*)d_in[3];
    const float* fl2 = (const float*)d_in[4];
    const float* fr2 = (const float*)d_in[5];
    const float* w_in0  = (const float*)d_in[6];
    const float* w_mid0 = (const float*)d_in[7];
    const float* w_out0 = (const float*)d_in[8];
    const float* w_in1  = (const float*)d_in[9];
    const float* w_mid1 = (const float*)d_in[10];
    const float* w_out1 = (const float*)d_in[11];
    const float* w_in2  = (const float*)d_in[12];
    const float* w_mid2 = (const float*)d_in[13];
    const float* w_out2 = (const float*)d_in[14];

    // padded arena layout (floats)
    float* act0a  = scr + 0;          // 8*16*14*34*82 = 4,996,096
    float* act0b  = scr + 4996096;
    float* cost0p = scr + 9992192;    // 8*14*34*82    =   312,256
    float* cost0u = scr + 10304448;   // 8*12*32*80    =   245,760
    float* act1a  = scr + 10550208;   // 8*4*7*66*162  = 2,395,008
    float* act1b  = scr + 12945216;
    float* cost1p = scr + 15340224;   // 8*7*66*162    =   598,752
    float* cost1u = scr + 15938976;   // 8*5*64*160    =   409,600
    float* act2a  = scr + 16348576;   // 8*4*7*130*322 = 9,376,640
    float* act2b  = scr + 25725216;
    float* cost2p = scr + 35101856;   // 8*7*130*322   = 2,344,160
    float* cost2u = scr + 37446016;   // 8*5*128*320   = 1,638,400
    float* dd0    = scr + 39084416;   //   20,480
    float* dd1    = scr + 39104896;   //   81,920
    float* dd2    = scr + 39186816;   //  327,680
    float* dtmp   = scr + 39514496;   // 8*512*320 = 1,310,720 (max of passes)

    float* out = (float*)d_out;
    const size_t NPX = (size_t)8 * 512 * 1280;
    float* pred0 = out;
    float* pred1 = out + NPX;
    float* pred2 = out + 2 * NPX;
    float* depth = out + 3 * NPX;

    // ---- scale 0 : D=12, H=32, W=80, 16 channels ----
    cost0_k<<<960, 256>>>(fl0, fr0, cost0p);
    conv3d_p<1, 16, 2, 12, 32, 80, true ><<<1920, 128>>>(cost0p, w_in0, act0a);
    conv3d_p<16, 16, 2, 12, 32, 80, true ><<<1920, 128>>>(act0a, w_mid0 + 0 * 6912, act0b);
    conv3d_p<16, 16, 2, 12, 32, 80, true ><<<1920, 128>>>(act0b, w_mid0 + 1 * 6912, act0a);
    conv3d_p<16, 16, 2, 12, 32, 80, true ><<<1920, 128>>>(act0a, w_mid0 + 2 * 6912, act0b);
    conv3d_p<16, 16, 2, 12, 32, 80, true ><<<1920, 128>>>(act0b, w_mid0 + 3 * 6912, act0a);
    conv3d_s<16, 12, 32, 80><<<480, 128>>>(act0a, w_out0, cost0u);
    dispreg_k<12, 0, 32, 80><<<80, 256>>>(cost0u, dd0, 16.0f);
    updown_k<32, 80, 8, 160, false, true><<<4096, 320>>>(dd0, nullptr, pred0, depth, dtmp);

    // ---- scale 1 : D=5, H=64, W=160, 4 channels ----
    costres_k<8, 64, 160><<<320, 256>>>(fl1, fr1, dtmp, cost1p, 0.125f);
    conv3d_p<1, 4, 2, 5, 64, 160, true ><<<800, 128>>>(cost1p, w_in1, act1a);
    conv3d_p<4, 4, 2, 5, 64, 160, true ><<<800, 128>>>(act1a, w_mid1 + 0 * 432, act1b);
    conv3d_p<4, 4, 2, 5, 64, 160, true ><<<800, 128>>>(act1b, w_mid1 + 1 * 432, act1a);
    conv3d_p<4, 4, 2, 5, 64, 160, true ><<<800, 128>>>(act1a, w_mid1 + 2 * 432, act1b);
    conv3d_p<4, 4, 2, 5, 64, 160, true ><<<800, 128>>>(act1b, w_mid1 + 3 * 432, act1a);
    conv3d_s<4, 5, 64, 160><<<800, 128>>>(act1a, w_out1, cost1u);
    dispreg_k<5, -2, 64, 160><<<320, 256>>>(cost1u, dd1, 8.0f);
    updown_k<64, 160, 4, 320, true, false><<<4096, 320>>>(dd1, pred0, pred1, nullptr, dtmp);

    // ---- scale 2 : D=5, H=128, W=320, 4 channels ----
    costres_k<4, 128, 320><<<1280, 256>>>(fl2, fr2, dtmp, cost2p, 0.25f);
    conv3d_p<1, 4, 2, 5, 128, 320, true ><<<3200, 128>>>(cost2p, w_in2, act2a);
    conv3d_p<4, 4, 2, 5, 128, 320, true ><<<3200, 128>>>(act2a, w_mid2 + 0 * 432, act2b);
    conv3d_p<4, 4, 2, 5, 128, 320, true ><<<3200, 128>>>(act2b, w_mid2 + 1 * 432, act2a);
    conv3d_p<4, 4, 2, 5, 128, 320, true ><<<3200, 128>>>(act2a, w_mid2 + 2 * 432, act2b);
    conv3d_p<4, 4, 2, 5, 128, 320, true ><<<3200, 128>>>(act2b, w_mid2 + 3 * 432, act2a);
    conv3d_s<4, 5, 128, 320><<<3200, 128>>>(act2a, w_out2, cost2u);
    dispreg_k<5, -2, 128, 320><<<1280, 256>>>(cost2u, dd2, 4.0f);
    up_k<128, 320, true, false><<<5120, 256>>>(dd2, pred1, pred2, nullptr);
}